// round 1
// baseline (speedup 1.0000x reference)
#include <cuda_runtime.h>

#define B_  4
#define T_  4096
#define TKP 1024        // pooled key length
#define DM  1024
#define HD  128

// ---------------- static device scratch (no allocations allowed) ----------------
__device__ float g_xp[B_ * TKP * DM];    // pooled x        (16 MB)
__device__ float g_Q [B_ * T_  * HD];    // Q (roped)       ( 8 MB)
__device__ float g_K [B_ * TKP * HD];    // K_pool (roped)  ( 2 MB)
__device__ float g_V [B_ * TKP * HD];    // V_pool          ( 2 MB)
__device__ float g_U [B_ * T_  * HD];    // unmasked branch ( 8 MB)
__device__ float g_cos[T_ * 64];
__device__ float g_sin[T_ * 64];

// ---------------- RoPE table: accurate double-precision sincos ----------------
__global__ void rope_table_k() {
    int t = blockIdx.x, i = threadIdx.x;
    double th = exp(((double)(-i) / 64.0) * log(10000.0));
    float arg = (float)t * (float)th;   // fp32 product, matching reference rounding
    double s, c;
    sincos((double)arg, &s, &c);
    g_cos[t * 64 + i] = (float)c;
    g_sin[t * 64 + i] = (float)s;
}

// ---------------- stride-4 mean pool of x:  (B,T,DM) -> (B,TKP,DM) ----------------
__global__ void pool_x_k(const float* __restrict__ x) {
    int f   = blockIdx.x * 256 + threadIdx.x;   // float4 index, exactly B*TKP*256
    int c4  = f & 255;
    int row = f >> 8;                            // b*1024 + tp
    int b   = row >> 10, tp = row & 1023;
    const float4* xi = (const float4*)x;
    size_t base = ((size_t)b * T_ + 4 * tp) * (DM / 4) + c4;
    float4 a = xi[base];
    float4 b2 = xi[base + (DM / 4)];
    float4 c = xi[base + 2 * (DM / 4)];
    float4 d = xi[base + 3 * (DM / 4)];
    float4 o;
    o.x = (a.x + b2.x + c.x + d.x) * 0.25f;
    o.y = (a.y + b2.y + c.y + d.y) * 0.25f;
    o.z = (a.z + b2.z + c.z + d.z) * 0.25f;
    o.w = (a.w + b2.w + c.w + d.w) * 0.25f;
    ((float4*)g_xp)[(size_t)row * (DM / 4) + c4] = o;
}

// ---------------- SGEMM: C[M,128] = A[M,1024] @ B[1024,128] ----------------
// 128x128 tile, BK=16, 256 threads, 8x8 microtile. blockIdx.z selects (B0,C0)/(B1,C1).
__global__ void __launch_bounds__(256) sgemm_k(
    const float* __restrict__ A,
    const float* __restrict__ B0, const float* __restrict__ B1,
    float* __restrict__ C0, float* __restrict__ C1)
{
    const float* Bm = (blockIdx.z == 0) ? B0 : B1;
    float*       Cm = (blockIdx.z == 0) ? C0 : C1;
    __shared__ __align__(16) float As[16][132];
    __shared__ __align__(16) float Bs[16][128];
    int tid = threadIdx.x;
    int tx = tid & 15, ty = tid >> 4;
    int m0 = blockIdx.x * 128;

    float acc[8][8];
#pragma unroll
    for (int i = 0; i < 8; i++)
#pragma unroll
        for (int j = 0; j < 8; j++) acc[i][j] = 0.f;

    for (int kb = 0; kb < DM; kb += 16) {
#pragma unroll
        for (int it = 0; it < 2; it++) {
            int f = it * 256 + tid;
            int row = f >> 2, c4 = f & 3;
            float4 v = *(const float4*)(A + (size_t)(m0 + row) * DM + kb + c4 * 4);
            As[c4 * 4 + 0][row] = v.x;
            As[c4 * 4 + 1][row] = v.y;
            As[c4 * 4 + 2][row] = v.z;
            As[c4 * 4 + 3][row] = v.w;
        }
#pragma unroll
        for (int it = 0; it < 2; it++) {
            int f = it * 256 + tid;
            int row = f >> 5, c4 = f & 31;
            *(float4*)(&Bs[row][c4 * 4]) = *(const float4*)(Bm + (size_t)(kb + row) * HD + c4 * 4);
        }
        __syncthreads();
#pragma unroll
        for (int kk = 0; kk < 16; kk++) {
            float a[8], bb[8];
            *(float4*)(a)      = *(const float4*)(&As[kk][ty * 8]);
            *(float4*)(a + 4)  = *(const float4*)(&As[kk][ty * 8 + 4]);
            *(float4*)(bb)     = *(const float4*)(&Bs[kk][tx * 8]);
            *(float4*)(bb + 4) = *(const float4*)(&Bs[kk][tx * 8 + 4]);
#pragma unroll
            for (int i = 0; i < 8; i++)
#pragma unroll
                for (int j = 0; j < 8; j++) acc[i][j] += a[i] * bb[j];
        }
        __syncthreads();
    }
#pragma unroll
    for (int i = 0; i < 8; i++) {
        float4 v0 = make_float4(acc[i][0], acc[i][1], acc[i][2], acc[i][3]);
        float4 v1 = make_float4(acc[i][4], acc[i][5], acc[i][6], acc[i][7]);
        float* cp = Cm + (size_t)(m0 + ty * 8 + i) * HD + tx * 8;
        *(float4*)(cp)     = v0;
        *(float4*)(cp + 4) = v1;
    }
}

// ---------------- RoPE in place ----------------
__global__ void rope_apply_k(float* __restrict__ X, int rows_pb) {
    int g = blockIdx.x * 256 + threadIdx.x;     // exactly B*rows_pb*64 threads
    int i = g & 63;
    int row = g >> 6;
    int pos = row % rows_pb;
    float c = g_cos[pos * 64 + i];
    float s = g_sin[pos * 64 + i];
    float* p = X + (size_t)row * HD;
    float x1 = p[i], x2 = p[i + 64];
    p[i]      = x1 * c - x2 * s;
    p[i + 64] = x2 * c + x1 * s;
}

// ---------------- attention ----------------
// CTA: 32 queries of batch b. Full 1024-key logits row in smem; one exp pass;
// masked (k<=q/4) + unmasked V-accumulation share the exponentials.
#define SCALE_INV 0.08838834764831845f   // 1/sqrt(128)
#define FMA4(acc, s, v) { acc.x += (s)*(v).x; acc.y += (s)*(v).y; acc.z += (s)*(v).z; acc.w += (s)*(v).w; }

__global__ void __launch_bounds__(256) attn_k(
    const float* __restrict__ Qg, const float* __restrict__ Kg,
    const float* __restrict__ Vg, float* __restrict__ Out,
    float* __restrict__ Ug, const float* __restrict__ alpha_p)
{
    extern __shared__ __align__(16) float sm[];
    float* Qs   = sm;                 // 32 x 132
    float* Ss   = sm + 32 * 132;      // 32 x 1028
    float* KV   = Ss + 32 * 1028;     // max(128*68, 64*132) = 8704
    float* mrow = KV + 8704;          // 32
    float* sful = mrow + 32;          // 32
    float* spre = sful + 32;          // 32
    float* red  = spre + 32;          // 256

    int tid = threadIdx.x;
    int q0  = blockIdx.x * 32;
    int b   = blockIdx.y;
    const float* Qb = Qg + ((size_t)b * T_ + q0) * HD;
    const float* Kb = Kg + (size_t)b * TKP * HD;
    const float* Vb = Vg + (size_t)b * TKP * HD;

    // ---- load Q tile, pre-scaled by 1/sqrt(HD) ----
#pragma unroll
    for (int it = 0; it < 4; it++) {
        int f = it * 256 + tid;
        int r = f >> 5, d4 = f & 31;
        float4 v = *(const float4*)(Qb + (size_t)r * HD + d4 * 4);
        v.x *= SCALE_INV; v.y *= SCALE_INV; v.z *= SCALE_INV; v.w *= SCALE_INV;
        *(float4*)(Qs + r * 132 + d4 * 4) = v;
    }

    // ---- phase 1: logits S[32][1024] ----
    {
        int kk = tid & 15, qq = tid >> 4;
        const float* qp0 = Qs + (2 * qq) * 132;
        const float* qp1 = qp0 + 132;
        for (int kt = 0; kt < 16; kt++) {
            __syncthreads();
            // K tile transposed into smem: KV[d][k], row stride 68
#pragma unroll
            for (int it = 0; it < 8; it++) {
                int f = it * 256 + tid;
                int kr = f & 63, d4 = f >> 6;
                float4 v = *(const float4*)(Kb + (size_t)(kt * 64 + kr) * HD + d4 * 4);
                KV[(d4 * 4 + 0) * 68 + kr] = v.x;
                KV[(d4 * 4 + 1) * 68 + kr] = v.y;
                KV[(d4 * 4 + 2) * 68 + kr] = v.z;
                KV[(d4 * 4 + 3) * 68 + kr] = v.w;
            }
            __syncthreads();
            float a00 = 0.f, a01 = 0.f, a02 = 0.f, a03 = 0.f;
            float a10 = 0.f, a11 = 0.f, a12 = 0.f, a13 = 0.f;
#pragma unroll 8
            for (int d = 0; d < 128; d++) {
                float4 kv = *(const float4*)(KV + d * 68 + (kk << 2));
                float a0 = qp0[d], a1 = qp1[d];
                a00 += a0 * kv.x; a01 += a0 * kv.y; a02 += a0 * kv.z; a03 += a0 * kv.w;
                a10 += a1 * kv.x; a11 += a1 * kv.y; a12 += a1 * kv.z; a13 += a1 * kv.w;
            }
            int kbidx = kt * 64 + (kk << 2);
            float* s0 = Ss + (2 * qq) * 1028 + kbidx;
            float* s1 = s0 + 1028;
            s0[0] = a00; s0[1] = a01; s0[2] = a02; s0[3] = a03;
            s1[0] = a10; s1[1] = a11; s1[2] = a12; s1[3] = a13;
        }
    }
    __syncthreads();

    // ---- phase 1.5: row max, exp transform, full + causal-prefix sums ----
    {
        int r = tid >> 3, c = tid & 7;
        float* srow = Ss + r * 1028;
        float mx = -1e30f;
#pragma unroll 8
        for (int j = 0; j < 128; j++) mx = fmaxf(mx, srow[c + 8 * j]);
        red[tid] = mx;
        __syncthreads();
        if (c == 0) {
            float m = red[tid];
#pragma unroll
            for (int j = 1; j < 8; j++) m = fmaxf(m, red[tid + j]);
            mrow[r] = m;
        }
        __syncthreads();
        float mr = mrow[r];
        int kmax = (q0 + r) >> 2;
        float sf = 0.f, sp = 0.f;
#pragma unroll 8
        for (int j = 0; j < 128; j++) {
            int idx = c + 8 * j;
            float e = __expf(srow[idx] - mr);
            srow[idx] = e;
            sf += e;
            if (idx <= kmax) sp += e;
        }
        red[tid] = sf;
        __syncthreads();
        if (c == 0) {
            float s = 0.f;
#pragma unroll
            for (int j = 0; j < 8; j++) s += red[tid + j];
            sful[r] = s;
        }
        __syncthreads();
        red[tid] = sp;
        __syncthreads();
        if (c == 0) {
            float s = 0.f;
#pragma unroll
            for (int j = 0; j < 8; j++) s += red[tid + j];
            spre[r] = s;
        }
        __syncthreads();
    }

    // ---- phase 2: O_full and O_prefix = P @ V ----
    {
        int dd = tid & 15, qq = tid >> 4;
        int r0 = 2 * qq, r1 = r0 + 1;
        int km0 = (q0 + r0) >> 2, km1 = (q0 + r1) >> 2;
        int kmaxCTA = (q0 + 31) >> 2;
        const float* e0p = Ss + r0 * 1028;
        const float* e1p = Ss + r1 * 1028;
        float4 z = make_float4(0.f, 0.f, 0.f, 0.f);
        float4 au0a = z, au0b = z, au1a = z, au1b = z;   // unmasked
        float4 ap0a = z, ap0b = z, ap1a = z, ap1b = z;   // masked prefix

        for (int kt = 0; kt < 16; kt++) {
            __syncthreads();
#pragma unroll
            for (int it = 0; it < 8; it++) {
                int f = it * 256 + tid;
                int d4 = f & 31, kr = f >> 5;
                *(float4*)(KV + kr * 132 + d4 * 4) =
                    *(const float4*)(Vb + (size_t)(kt * 64 + kr) * HD + d4 * 4);
            }
            __syncthreads();
            if (kt * 64 <= kmaxCTA) {
#pragma unroll 4
                for (int k = 0; k < 64; k++) {
                    int kg = kt * 64 + k;
                    float e0 = e0p[kg], e1 = e1p[kg];
                    const float* vp = KV + k * 132 + dd * 8;
                    float4 va = *(const float4*)(vp);
                    float4 vb = *(const float4*)(vp + 4);
                    FMA4(au0a, e0, va); FMA4(au0b, e0, vb);
                    FMA4(au1a, e1, va); FMA4(au1b, e1, vb);
                    float f0 = (kg <= km0) ? e0 : 0.f;
                    float f1 = (kg <= km1) ? e1 : 0.f;
                    FMA4(ap0a, f0, va); FMA4(ap0b, f0, vb);
                    FMA4(ap1a, f1, va); FMA4(ap1b, f1, vb);
                }
            } else {
#pragma unroll 4
                for (int k = 0; k < 64; k++) {
                    int kg = kt * 64 + k;
                    float e0 = e0p[kg], e1 = e1p[kg];
                    const float* vp = KV + k * 132 + dd * 8;
                    float4 va = *(const float4*)(vp);
                    float4 vb = *(const float4*)(vp + 4);
                    FMA4(au0a, e0, va); FMA4(au0b, e0, vb);
                    FMA4(au1a, e1, va); FMA4(au1b, e1, vb);
                }
            }
        }

        float alpha = 1.f / (1.f + __expf(-alpha_p[0]));
        float wp0 = alpha / spre[r0];
        float wp1 = alpha / spre[r1];
        float wu0 = (1.f - alpha) / sful[r0];
        float wu1 = (1.f - alpha) / sful[r1];

        float* op0 = Out + ((size_t)b * T_ + q0 + r0) * HD + dd * 8;
        float* op1 = Out + ((size_t)b * T_ + q0 + r1) * HD + dd * 8;
        float* up0 = Ug  + ((size_t)b * T_ + (T_ - 1 - (q0 + r0))) * HD + dd * 8;
        float* up1 = Ug  + ((size_t)b * T_ + (T_ - 1 - (q0 + r1))) * HD + dd * 8;

        *(float4*)(op0)     = make_float4(ap0a.x * wp0, ap0a.y * wp0, ap0a.z * wp0, ap0a.w * wp0);
        *(float4*)(op0 + 4) = make_float4(ap0b.x * wp0, ap0b.y * wp0, ap0b.z * wp0, ap0b.w * wp0);
        *(float4*)(op1)     = make_float4(ap1a.x * wp1, ap1a.y * wp1, ap1a.z * wp1, ap1a.w * wp1);
        *(float4*)(op1 + 4) = make_float4(ap1b.x * wp1, ap1b.y * wp1, ap1b.z * wp1, ap1b.w * wp1);
        *(float4*)(up0)     = make_float4(au0a.x * wu0, au0a.y * wu0, au0a.z * wu0, au0a.w * wu0);
        *(float4*)(up0 + 4) = make_float4(au0b.x * wu0, au0b.y * wu0, au0b.z * wu0, au0b.w * wu0);
        *(float4*)(up1)     = make_float4(au1a.x * wu1, au1a.y * wu1, au1a.z * wu1, au1a.w * wu1);
        *(float4*)(up1 + 4) = make_float4(au1b.x * wu1, au1b.y * wu1, au1b.z * wu1, au1b.w * wu1);
    }
}

// ---------------- combine: out[b,q] += (1-a)*unmasked[b, T-1-q] (already scattered) ----------------
__global__ void combine_k(float* __restrict__ out) {
    int f = blockIdx.x * 256 + threadIdx.x;    // exactly B*T*HD/4 threads
    float4* o = (float4*)out;
    const float4* u = (const float4*)g_U;
    float4 a = o[f], bv = u[f];
    a.x += bv.x; a.y += bv.y; a.z += bv.z; a.w += bv.w;
    o[f] = a;
}

// ---------------- launch ----------------
extern "C" void kernel_launch(void* const* d_in, const int* in_sizes, int n_in,
                              void* d_out, int out_size) {
    const float* x  = (const float*)d_in[0];
    const float* Wq = (const float*)d_in[1];
    const float* Wk = (const float*)d_in[2];
    const float* Wv = (const float*)d_in[3];
    const float* fa = (const float*)d_in[9];
    float* out = (float*)d_out;

    void *pxp, *pq, *pk, *pv, *pu;
    cudaGetSymbolAddress(&pxp, g_xp);
    cudaGetSymbolAddress(&pq,  g_Q);
    cudaGetSymbolAddress(&pk,  g_K);
    cudaGetSymbolAddress(&pv,  g_V);
    cudaGetSymbolAddress(&pu,  g_U);

    const int ATTN_SMEM = (32 * 132 + 32 * 1028 + 8704 + 96 + 256) * 4;  // 184704 B
    cudaFuncSetAttribute(attn_k, cudaFuncAttributeMaxDynamicSharedMemorySize, ATTN_SMEM);

    rope_table_k<<<T_, 64>>>();
    pool_x_k<<<(B_ * TKP * (DM / 4)) / 256, 256>>>(x);
    sgemm_k<<<dim3(T_ * B_ / 128, 1, 1), 256>>>(x, Wq, Wq, (float*)pq, (float*)pq);
    sgemm_k<<<dim3(B_ * TKP / 128, 1, 2), 256>>>((const float*)pxp, Wk, Wv, (float*)pk, (float*)pv);
    rope_apply_k<<<(B_ * T_ * 64) / 256, 256>>>((float*)pq, T_);
    rope_apply_k<<<(B_ * TKP * 64) / 256, 256>>>((float*)pk, TKP);
    attn_k<<<dim3(T_ / 32, B_), 256, ATTN_SMEM>>>((const float*)pq, (const float*)pk,
                                                  (const float*)pv, out, (float*)pu, fa);
    combine_k<<<(B_ * T_ * HD / 4) / 256, 256>>>(out);
}

// round 2
// speedup vs baseline: 2.1551x; 2.1551x over previous
#include <cuda_runtime.h>
#include <cstdint>

#define B_  4
#define T_  4096
#define TKP 1024        // pooled key length
#define DM  1024
#define HD  128
#define SCALE_INV 0.08838834764831845f   // 1/sqrt(128)

// ---------------- static device scratch ----------------
__device__ float g_xp[B_ * TKP * DM];    // pooled x
__device__ float g_Q [B_ * T_  * HD];
__device__ float g_K [B_ * TKP * HD];
__device__ float g_V [B_ * TKP * HD];
__device__ float g_U [B_ * T_  * HD];
__device__ float g_cos[T_ * 64];
__device__ float g_sin[T_ * 64];

// ---------------- helpers ----------------
__device__ __forceinline__ unsigned f2t(float x) {
    unsigned r; asm("cvt.rna.tf32.f32 %0, %1;" : "=r"(r) : "f"(x)); return r;
}
__device__ __forceinline__ float f2tf(float x) { return __uint_as_float(f2t(x)); }

__device__ __forceinline__ void mma8(float& d0, float& d1, float& d2, float& d3,
                                     unsigned a0, unsigned a1, unsigned a2, unsigned a3,
                                     unsigned b0, unsigned b1) {
    asm volatile("mma.sync.aligned.m16n8k8.row.col.f32.tf32.tf32.f32 "
                 "{%0,%1,%2,%3},{%4,%5,%6,%7},{%8,%9},{%0,%1,%2,%3};"
                 : "+f"(d0), "+f"(d1), "+f"(d2), "+f"(d3)
                 : "r"(a0), "r"(a1), "r"(a2), "r"(a3), "r"(b0), "r"(b1));
}

// ---------------- RoPE table (double-precision sincos) ----------------
__global__ void rope_table_k() {
    int t = blockIdx.x, i = threadIdx.x;
    double th = exp(((double)(-i) / 64.0) * log(10000.0));
    float arg = (float)t * (float)th;
    double s, c;
    sincos((double)arg, &s, &c);
    g_cos[t * 64 + i] = (float)c;
    g_sin[t * 64 + i] = (float)s;
}

// ---------------- stride-4 mean pool ----------------
__global__ void pool_x_k(const float* __restrict__ x) {
    int f   = blockIdx.x * 256 + threadIdx.x;
    int c4  = f & 255;
    int row = f >> 8;
    int b   = row >> 10, tp = row & 1023;
    const float4* xi = (const float4*)x;
    size_t base = ((size_t)b * T_ + 4 * tp) * (DM / 4) + c4;
    float4 a = xi[base];
    float4 b2 = xi[base + (DM / 4)];
    float4 c = xi[base + 2 * (DM / 4)];
    float4 d = xi[base + 3 * (DM / 4)];
    float4 o;
    o.x = (a.x + b2.x + c.x + d.x) * 0.25f;
    o.y = (a.y + b2.y + c.y + d.y) * 0.25f;
    o.z = (a.z + b2.z + c.z + d.z) * 0.25f;
    o.w = (a.w + b2.w + c.w + d.w) * 0.25f;
    ((float4*)g_xp)[(size_t)row * (DM / 4) + c4] = o;
}

// ---------------- fused scalar projection GEMM: Q|K|V in one grid ----------------
// grid 192: [0,128) Q = x@Wq; [128,160) K = xp@Wk; [160,192) V = xp@Wv
__global__ void __launch_bounds__(256, 2) proj_k(
    const float* __restrict__ x,
    const float* __restrict__ Wq, const float* __restrict__ Wk, const float* __restrict__ Wv)
{
    int bid = blockIdx.x;
    const float* A; const float* Wm; float* Cm; int m0;
    if (bid < 128)      { A = x;    Wm = Wq; Cm = g_Q; m0 = bid * 128; }
    else if (bid < 160) { A = g_xp; Wm = Wk; Cm = g_K; m0 = (bid - 128) * 128; }
    else                { A = g_xp; Wm = Wv; Cm = g_V; m0 = (bid - 160) * 128; }

    __shared__ __align__(16) float As[16][132];
    __shared__ __align__(16) float Bs[16][128];
    int tid = threadIdx.x;
    int tx = tid & 15, ty = tid >> 4;

    float acc[8][8];
#pragma unroll
    for (int i = 0; i < 8; i++)
#pragma unroll
        for (int j = 0; j < 8; j++) acc[i][j] = 0.f;

    for (int kb = 0; kb < DM; kb += 16) {
#pragma unroll
        for (int it = 0; it < 2; it++) {
            int f = it * 256 + tid;
            int row = f >> 2, c4 = f & 3;
            float4 v = *(const float4*)(A + (size_t)(m0 + row) * DM + kb + c4 * 4);
            As[c4 * 4 + 0][row] = v.x;
            As[c4 * 4 + 1][row] = v.y;
            As[c4 * 4 + 2][row] = v.z;
            As[c4 * 4 + 3][row] = v.w;
        }
#pragma unroll
        for (int it = 0; it < 2; it++) {
            int f = it * 256 + tid;
            int row = f >> 5, c4 = f & 31;
            *(float4*)(&Bs[row][c4 * 4]) = *(const float4*)(Wm + (size_t)(kb + row) * HD + c4 * 4);
        }
        __syncthreads();
#pragma unroll
        for (int kk = 0; kk < 16; kk++) {
            float a[8], bb[8];
            *(float4*)(a)      = *(const float4*)(&As[kk][ty * 8]);
            *(float4*)(a + 4)  = *(const float4*)(&As[kk][ty * 8 + 4]);
            *(float4*)(bb)     = *(const float4*)(&Bs[kk][tx * 8]);
            *(float4*)(bb + 4) = *(const float4*)(&Bs[kk][tx * 8 + 4]);
#pragma unroll
            for (int i = 0; i < 8; i++)
#pragma unroll
                for (int j = 0; j < 8; j++) acc[i][j] += a[i] * bb[j];
        }
        __syncthreads();
    }
#pragma unroll
    for (int i = 0; i < 8; i++) {
        float4 v0 = make_float4(acc[i][0], acc[i][1], acc[i][2], acc[i][3]);
        float4 v1 = make_float4(acc[i][4], acc[i][5], acc[i][6], acc[i][7]);
        float* cp = Cm + (size_t)(m0 + ty * 8 + i) * HD + tx * 8;
        *(float4*)(cp)     = v0;
        *(float4*)(cp + 4) = v1;
    }
}

// ---------------- RoPE in place (which: 0 -> g_Q rows T_, 1 -> g_K rows TKP) ----------------
__global__ void rope_apply_k(int which, int rows_pb) {
    float* X = which ? g_K : g_Q;
    int g = blockIdx.x * 256 + threadIdx.x;
    int i = g & 63;
    int row = g >> 6;
    int pos = row % rows_pb;
    float c = g_cos[pos * 64 + i];
    float s = g_sin[pos * 64 + i];
    float* p = X + (size_t)row * HD;
    float x1 = p[i], x2 = p[i + 64];
    p[i]      = x1 * c - x2 * s;
    p[i + 64] = x2 * c + x1 * s;
}

// ---------------- attention: TF32 mma, 32 queries/CTA, shared-exp dual softmax ----------------
__global__ void __launch_bounds__(256) attn_k(const float* __restrict__ alpha_p,
                                              float* __restrict__ Out)
{
    extern __shared__ __align__(16) float sm[];
    float* Qs   = sm;                   // 32 x 132
    float* Ss   = sm + 32 * 132;        // 32 x 1028
    float* KV   = Ss + 32 * 1028;       // K tile 64x132 / V tile 64x136 (8704 floats)
    float* mrow = KV + 64 * 136;        // 32
    float* sful = mrow + 32;            // 32
    float* spre = sful + 32;            // 32
    float* red  = spre + 32;            // 256

    int tid  = threadIdx.x;
    int lane = tid & 31, wid = tid >> 5;
    int gid  = lane >> 2, tig = lane & 3;
    int q0 = blockIdx.x * 32;
    int b  = blockIdx.y;
    const float* Qb = g_Q + ((size_t)b * T_ + q0) * HD;
    const float* Kb = g_K + (size_t)b * TKP * HD;
    const float* Vb = g_V + (size_t)b * TKP * HD;

    // ---- load Q tile (scaled + tf32-rounded) ----
#pragma unroll
    for (int it = 0; it < 4; it++) {
        int f = it * 256 + tid;
        int r = f >> 5, d4 = f & 31;
        float4 v = *(const float4*)(Qb + (size_t)r * HD + d4 * 4);
        float* p = Qs + r * 132 + d4 * 4;
        p[0] = f2tf(v.x * SCALE_INV);
        p[1] = f2tf(v.y * SCALE_INV);
        p[2] = f2tf(v.z * SCALE_INV);
        p[3] = f2tf(v.w * SCALE_INV);
    }
    __syncthreads();

    int m0  = (wid & 1) * 16;
    int row0 = m0 + gid;                 // local q row of c0/c1 (c2/c3 at +8)

    // ---- phase 1: S = Q @ K^T (tf32 mma) ----
    {
        int n0w = (wid >> 1) * 16;       // 16 keys per warp per 64-key tile
        unsigned a[16][4];
#pragma unroll
        for (int ks = 0; ks < 16; ks++) {
            const float* qp = Qs + row0 * 132 + ks * 8 + tig;
            a[ks][0] = __float_as_uint(qp[0]);
            a[ks][1] = __float_as_uint(qp[8 * 132]);
            a[ks][2] = __float_as_uint(qp[4]);
            a[ks][3] = __float_as_uint(qp[8 * 132 + 4]);
        }
        for (int kt = 0; kt < 16; kt++) {
            __syncthreads();
#pragma unroll
            for (int it = 0; it < 8; it++) {
                int f = it * 256 + tid;
                int kr = f >> 5, d4 = f & 31;
                float4 v = *(const float4*)(Kb + (size_t)(kt * 64 + kr) * HD + d4 * 4);
                float* p = KV + kr * 132 + d4 * 4;
                p[0] = f2tf(v.x); p[1] = f2tf(v.y); p[2] = f2tf(v.z); p[3] = f2tf(v.w);
            }
            __syncthreads();
            float c0[4] = {0.f, 0.f, 0.f, 0.f};
            float c1[4] = {0.f, 0.f, 0.f, 0.f};
#pragma unroll
            for (int ks = 0; ks < 16; ks++) {
                const float* kp0 = KV + (n0w + gid) * 132 + ks * 8 + tig;
                const float* kp1 = kp0 + 8 * 132;
                unsigned b00 = __float_as_uint(kp0[0]), b01 = __float_as_uint(kp0[4]);
                unsigned b10 = __float_as_uint(kp1[0]), b11 = __float_as_uint(kp1[4]);
                mma8(c0[0], c0[1], c0[2], c0[3], a[ks][0], a[ks][1], a[ks][2], a[ks][3], b00, b01);
                mma8(c1[0], c1[1], c1[2], c1[3], a[ks][0], a[ks][1], a[ks][2], a[ks][3], b10, b11);
            }
            float* s0 = Ss + row0 * 1028 + kt * 64 + n0w + 2 * tig;
            float* s1 = s0 + 8 * 1028;
            s0[0] = c0[0]; s0[1] = c0[1]; s0[8] = c1[0]; s0[9] = c1[1];
            s1[0] = c0[2]; s1[1] = c0[3]; s1[8] = c1[2]; s1[9] = c1[3];
        }
    }
    __syncthreads();

    // ---- phase 1.5: row max, exp, full + causal-prefix sums ----
    {
        int r = tid >> 3, c = tid & 7;
        float* srow = Ss + r * 1028;
        float mx = -1e30f;
#pragma unroll 8
        for (int j = 0; j < 128; j++) mx = fmaxf(mx, srow[c + 8 * j]);
        red[tid] = mx;
        __syncthreads();
        if (c == 0) {
            float m = red[tid];
#pragma unroll
            for (int j = 1; j < 8; j++) m = fmaxf(m, red[tid + j]);
            mrow[r] = m;
        }
        __syncthreads();
        float mr = mrow[r];
        int kmax = (q0 + r) >> 2;
        float sf = 0.f, sp = 0.f;
#pragma unroll 8
        for (int j = 0; j < 128; j++) {
            int idx = c + 8 * j;
            float e = __expf(srow[idx] - mr);
            srow[idx] = e;
            sf += e;
            if (idx <= kmax) sp += e;
        }
        red[tid] = sf;
        __syncthreads();
        if (c == 0) {
            float s = 0.f;
#pragma unroll
            for (int j = 0; j < 8; j++) s += red[tid + j];
            sful[r] = s;
        }
        __syncthreads();
        red[tid] = sp;
        __syncthreads();
        if (c == 0) {
            float s = 0.f;
#pragma unroll
            for (int j = 0; j < 8; j++) s += red[tid + j];
            spre[r] = s;
        }
        __syncthreads();
    }

    // ---- phase 2: O_full and O_prefix = P @ V (tf32 mma, masked frags) ----
    {
        int n0 = (wid >> 1) * 32;            // 32 d-cols per warp
        int kmaxCTA = (q0 + 31) >> 2;
        int kmax0 = (q0 + row0) >> 2;
        int kmax1 = (q0 + row0 + 8) >> 2;
        float u [4][4];
        float mk[4][4];
#pragma unroll
        for (int i = 0; i < 4; i++)
#pragma unroll
            for (int j = 0; j < 4; j++) { u[i][j] = 0.f; mk[i][j] = 0.f; }

        for (int kt = 0; kt < 16; kt++) {
            __syncthreads();
#pragma unroll
            for (int it = 0; it < 8; it++) {
                int f = it * 256 + tid;
                int kr = f >> 5, d4 = f & 31;
                float4 v = *(const float4*)(Vb + (size_t)(kt * 64 + kr) * HD + d4 * 4);
                float* p = KV + kr * 136 + d4 * 4;
                p[0] = f2tf(v.x); p[1] = f2tf(v.y); p[2] = f2tf(v.z); p[3] = f2tf(v.w);
            }
            __syncthreads();
            int kbase = kt * 64;
#pragma unroll
            for (int ks = 0; ks < 8; ks++) {
                int k0g = kbase + ks * 8;
                const float* ap = Ss + row0 * 1028 + k0g + tig;
                unsigned a0 = f2t(ap[0]);
                unsigned a1 = f2t(ap[8 * 1028]);
                unsigned a2 = f2t(ap[4]);
                unsigned a3 = f2t(ap[8 * 1028 + 4]);
                unsigned am0 = (k0g + tig     <= kmax0) ? a0 : 0u;
                unsigned am1 = (k0g + tig     <= kmax1) ? a1 : 0u;
                unsigned am2 = (k0g + tig + 4 <= kmax0) ? a2 : 0u;
                unsigned am3 = (k0g + tig + 4 <= kmax1) ? a3 : 0u;
                bool doM = (k0g <= kmaxCTA);
#pragma unroll
                for (int nt = 0; nt < 4; nt++) {
                    const float* vp = KV + (ks * 8 + tig) * 136 + n0 + nt * 8 + gid;
                    unsigned b0 = __float_as_uint(vp[0]);
                    unsigned b1 = __float_as_uint(vp[4 * 136]);
                    mma8(u[nt][0], u[nt][1], u[nt][2], u[nt][3], a0, a1, a2, a3, b0, b1);
                    if (doM)
                        mma8(mk[nt][0], mk[nt][1], mk[nt][2], mk[nt][3], am0, am1, am2, am3, b0, b1);
                }
            }
        }

        float alpha = 1.f / (1.f + __expf(-alpha_p[0]));
        float wp0 = alpha / spre[row0];
        float wp1 = alpha / spre[row0 + 8];
        float wu0 = (1.f - alpha) / sful[row0];
        float wu1 = (1.f - alpha) / sful[row0 + 8];

        int qg0 = q0 + row0, qg1 = q0 + row0 + 8;
        float* O0 = Out + ((size_t)b * T_ + qg0) * HD;
        float* O1 = Out + ((size_t)b * T_ + qg1) * HD;
        float* U0 = g_U + ((size_t)b * T_ + (T_ - 1 - qg0)) * HD;
        float* U1 = g_U + ((size_t)b * T_ + (T_ - 1 - qg1)) * HD;
#pragma unroll
        for (int nt = 0; nt < 4; nt++) {
            int col = n0 + nt * 8 + 2 * tig;
            *(float2*)(O0 + col) = make_float2(mk[nt][0] * wp0, mk[nt][1] * wp0);
            *(float2*)(O1 + col) = make_float2(mk[nt][2] * wp1, mk[nt][3] * wp1);
            *(float2*)(U0 + col) = make_float2(u[nt][0] * wu0, u[nt][1] * wu0);
            *(float2*)(U1 + col) = make_float2(u[nt][2] * wu1, u[nt][3] * wu1);
        }
    }
}

// ---------------- combine ----------------
__global__ void combine_k(float* __restrict__ out) {
    int f = blockIdx.x * 256 + threadIdx.x;
    float4* o = (float4*)out;
    const float4* u = (const float4*)g_U;
    float4 a = o[f], bv = u[f];
    a.x += bv.x; a.y += bv.y; a.z += bv.z; a.w += bv.w;
    o[f] = a;
}

// ---------------- launch ----------------
extern "C" void kernel_launch(void* const* d_in, const int* in_sizes, int n_in,
                              void* d_out, int out_size) {
    const float* x  = (const float*)d_in[0];
    const float* Wq = (const float*)d_in[1];
    const float* Wk = (const float*)d_in[2];
    const float* Wv = (const float*)d_in[3];
    const float* fa = (const float*)d_in[9];
    float* out = (float*)d_out;

    const int ATTN_SMEM = (32 * 132 + 32 * 1028 + 64 * 136 + 96 + 256) * 4;  // 184704 B
    cudaFuncSetAttribute(attn_k, cudaFuncAttributeMaxDynamicSharedMemorySize, ATTN_SMEM);

    rope_table_k<<<T_, 64>>>();
    pool_x_k<<<(B_ * TKP * (DM / 4)) / 256, 256>>>(x);
    proj_k<<<192, 256>>>(x, Wq, Wk, Wv);
    rope_apply_k<<<(B_ * T_ * 64) / 256, 256>>>(0, T_);
    rope_apply_k<<<(B_ * TKP * 64) / 256, 256>>>(1, TKP);
    attn_k<<<dim3(T_ / 32, B_), 256, ATTN_SMEM>>>(fa, out);
    combine_k<<<(B_ * T_ * HD / 4) / 256, 256>>>(out);
}

// round 3
// speedup vs baseline: 2.9805x; 1.3830x over previous
#include <cuda_runtime.h>
#include <cstdint>

#define B_  4
#define T_  4096
#define TKP 1024
#define DM  1024
#define HD  128
#define SCALE_INV 0.08838834764831845f   // 1/sqrt(128)

// ---------------- static device scratch ----------------
__device__ float  g_xp[B_ * TKP * DM];
__device__ float  g_Q [B_ * T_  * HD];
__device__ float  g_K [B_ * TKP * HD];
__device__ float  g_V [B_ * TKP * HD];
__device__ float  g_U [B_ * T_  * HD];
__device__ float  g_cos[T_ * 64];
__device__ float  g_sin[T_ * 64];
__device__ double g_theta[64];

// ---------------- helpers ----------------
__device__ __forceinline__ unsigned f2t(float x) {
    unsigned r; asm("cvt.rna.tf32.f32 %0, %1;" : "=r"(r) : "f"(x)); return r;
}
__device__ __forceinline__ float f2tf(float x) { return __uint_as_float(f2t(x)); }
__device__ __forceinline__ float4 f2tf4(float4 v) {
    return make_float4(f2tf(v.x), f2tf(v.y), f2tf(v.z), f2tf(v.w));
}

__device__ __forceinline__ void mma8(float* d,
                                     float a0, float a1, float a2, float a3,
                                     float b0, float b1) {
    asm volatile("mma.sync.aligned.m16n8k8.row.col.f32.tf32.tf32.f32 "
                 "{%0,%1,%2,%3},{%4,%5,%6,%7},{%8,%9},{%0,%1,%2,%3};"
                 : "+f"(d[0]), "+f"(d[1]), "+f"(d[2]), "+f"(d[3])
                 : "r"(__float_as_uint(a0)), "r"(__float_as_uint(a1)),
                   "r"(__float_as_uint(a2)), "r"(__float_as_uint(a3)),
                   "r"(__float_as_uint(b0)), "r"(__float_as_uint(b1)));
}

// ---------------- RoPE tables ----------------
__global__ void theta_k() {
    int i = threadIdx.x;
    g_theta[i] = exp(((double)(-i) / 64.0) * log(10000.0));
}
__global__ void rope_table_k() {
    int t = blockIdx.x, i = threadIdx.x;
    float thf = (float)g_theta[i];
    float arg = (float)t * thf;          // fp32 product, matching reference
    // accurate range reduction in double, then float sincos
    const double TWO_PI  = 6.283185307179586476925286766559;
    const double INV2PI  = 0.15915494309189533576888376337251;
    double da = (double)arg;
    double k  = rint(da * INV2PI);
    float  r  = (float)(da - k * TWO_PI);
    g_cos[t * 64 + i] = cosf(r);
    g_sin[t * 64 + i] = sinf(r);
}

// ---------------- stride-4 mean pool ----------------
__global__ void pool_x_k(const float* __restrict__ x) {
    int f   = blockIdx.x * 256 + threadIdx.x;
    int c4  = f & 255;
    int row = f >> 8;
    int b   = row >> 10, tp = row & 1023;
    const float4* xi = (const float4*)x;
    size_t base = ((size_t)b * T_ + 4 * tp) * (DM / 4) + c4;
    float4 a = xi[base];
    float4 b2 = xi[base + (DM / 4)];
    float4 c = xi[base + 2 * (DM / 4)];
    float4 d = xi[base + 3 * (DM / 4)];
    float4 o;
    o.x = (a.x + b2.x + c.x + d.x) * 0.25f;
    o.y = (a.y + b2.y + c.y + d.y) * 0.25f;
    o.z = (a.z + b2.z + c.z + d.z) * 0.25f;
    o.w = (a.w + b2.w + c.w + d.w) * 0.25f;
    ((float4*)g_xp)[(size_t)row * (DM / 4) + c4] = o;
}

// ---------------- 3xTF32 projection GEMM: Q|K|V fused ----------------
// grid 192: [0,128) Q = x@Wq; [128,160) K = xp@Wk; [160,192) V = xp@Wv
// C[128,128] tile, 256 thr, warp = 32 rows x 64 cols, 3xTF32 split.
#define AST 20      // A smem stride [m][AST]
#define BST 136     // B smem stride [k][BST]
__global__ void __launch_bounds__(256, 2) proj_k(
    const float* __restrict__ x,
    const float* __restrict__ Wq, const float* __restrict__ Wk, const float* __restrict__ Wv)
{
    int bid = blockIdx.x;
    const float* A; const float* Wm; float* Cm; int m0;
    if (bid < 128)      { A = x;    Wm = Wq; Cm = g_Q; m0 = bid * 128; }
    else if (bid < 160) { A = g_xp; Wm = Wk; Cm = g_K; m0 = (bid - 128) * 128; }
    else                { A = g_xp; Wm = Wv; Cm = g_V; m0 = (bid - 160) * 128; }

    __shared__ __align__(16) float Ah[128 * AST];
    __shared__ __align__(16) float Al[128 * AST];
    __shared__ __align__(16) float Bh[16 * BST];
    __shared__ __align__(16) float Bl[16 * BST];

    int tid  = threadIdx.x;
    int lane = tid & 31, wid = tid >> 5;
    int gid  = lane >> 2, tig = lane & 3;
    int wm = wid >> 1, wn = wid & 1;

    float C[2][8][4];
#pragma unroll
    for (int mf = 0; mf < 2; mf++)
#pragma unroll
        for (int nf = 0; nf < 8; nf++)
#pragma unroll
            for (int j = 0; j < 4; j++) C[mf][nf][j] = 0.f;

    for (int kb = 0; kb < DM; kb += 16) {
        __syncthreads();
        // stage A tile [128 rows][16 k] -> Ah/Al [m][AST]
#pragma unroll
        for (int it = 0; it < 2; it++) {
            int f = it * 256 + tid;
            int r = f >> 2, c4 = f & 3;
            float4 v = *(const float4*)(A + (size_t)(m0 + r) * DM + kb + c4 * 4);
            float4 h = f2tf4(v);
            float4 l = f2tf4(make_float4(v.x - h.x, v.y - h.y, v.z - h.z, v.w - h.w));
            *(float4*)(Ah + r * AST + c4 * 4) = h;
            *(float4*)(Al + r * AST + c4 * 4) = l;
        }
        // stage B tile [16 k][128 n] -> Bh/Bl [k][BST]
#pragma unroll
        for (int it = 0; it < 2; it++) {
            int f = it * 256 + tid;
            int r = f >> 5, c4 = f & 31;
            float4 v = *(const float4*)(Wm + (size_t)(kb + r) * HD + c4 * 4);
            float4 h = f2tf4(v);
            float4 l = f2tf4(make_float4(v.x - h.x, v.y - h.y, v.z - h.z, v.w - h.w));
            *(float4*)(Bh + r * BST + c4 * 4) = h;
            *(float4*)(Bl + r * BST + c4 * 4) = l;
        }
        __syncthreads();
#pragma unroll
        for (int ks = 0; ks < 2; ks++) {
            int k0 = ks * 8;
            float ah[2][4], al[2][4];
#pragma unroll
            for (int mf = 0; mf < 2; mf++) {
                int mb = wm * 32 + mf * 16;
                ah[mf][0] = Ah[(mb + gid)     * AST + k0 + tig];
                ah[mf][1] = Ah[(mb + gid + 8) * AST + k0 + tig];
                ah[mf][2] = Ah[(mb + gid)     * AST + k0 + tig + 4];
                ah[mf][3] = Ah[(mb + gid + 8) * AST + k0 + tig + 4];
                al[mf][0] = Al[(mb + gid)     * AST + k0 + tig];
                al[mf][1] = Al[(mb + gid + 8) * AST + k0 + tig];
                al[mf][2] = Al[(mb + gid)     * AST + k0 + tig + 4];
                al[mf][3] = Al[(mb + gid + 8) * AST + k0 + tig + 4];
            }
#pragma unroll
            for (int nf = 0; nf < 8; nf++) {
                int nb = wn * 64 + nf * 8 + gid;
                float bh0 = Bh[(k0 + tig)     * BST + nb];
                float bh1 = Bh[(k0 + tig + 4) * BST + nb];
                float bl0 = Bl[(k0 + tig)     * BST + nb];
                float bl1 = Bl[(k0 + tig + 4) * BST + nb];
#pragma unroll
                for (int mf = 0; mf < 2; mf++) {
                    mma8(C[mf][nf], ah[mf][0], ah[mf][1], ah[mf][2], ah[mf][3], bh0, bh1);
                    mma8(C[mf][nf], al[mf][0], al[mf][1], al[mf][2], al[mf][3], bh0, bh1);
                    mma8(C[mf][nf], ah[mf][0], ah[mf][1], ah[mf][2], ah[mf][3], bl0, bl1);
                }
            }
        }
    }
#pragma unroll
    for (int mf = 0; mf < 2; mf++) {
        int r0 = m0 + wm * 32 + mf * 16 + gid;
#pragma unroll
        for (int nf = 0; nf < 8; nf++) {
            int col = wn * 64 + nf * 8 + 2 * tig;
            *(float2*)(Cm + (size_t)r0 * HD + col)       = make_float2(C[mf][nf][0], C[mf][nf][1]);
            *(float2*)(Cm + (size_t)(r0 + 8) * HD + col) = make_float2(C[mf][nf][2], C[mf][nf][3]);
        }
    }
}

// ---------------- RoPE in place, vectorized ----------------
__global__ void rope2_k(int which) {
    float* X = which ? g_K : g_Q;
    int mask = which ? (TKP - 1) : (T_ - 1);
    int g = blockIdx.x * 256 + threadIdx.x;
    int i4 = g & 15;
    int row = g >> 4;
    int pos = row & mask;
    float4 c  = *(float4*)(g_cos + pos * 64 + i4 * 4);
    float4 s  = *(float4*)(g_sin + pos * 64 + i4 * 4);
    float* p  = X + (size_t)row * HD + i4 * 4;
    float4 x1 = *(float4*)(p);
    float4 x2 = *(float4*)(p + 64);
    float4 o1 = make_float4(x1.x * c.x - x2.x * s.x, x1.y * c.y - x2.y * s.y,
                            x1.z * c.z - x2.z * s.z, x1.w * c.w - x2.w * s.w);
    float4 o2 = make_float4(x2.x * c.x + x1.x * s.x, x2.y * c.y + x1.y * s.y,
                            x2.z * c.z + x1.z * s.z, x2.w * c.w + x1.w * s.w);
    *(float4*)(p)      = o1;
    *(float4*)(p + 64) = o2;
}

// ---------------- flash attention, dual softmax, prefix/extra split ----------------
// CTA = 64 queries, 8 warps. Warp: rows rg*16 (rg=wid>>1), S-keys half*32 / PV-cols half*64.
#define QST 132
#define KST 136
#define PST 68
__global__ void __launch_bounds__(256, 2) attn_k(const float* __restrict__ alpha_p,
                                                 float* __restrict__ Out)
{
    extern __shared__ __align__(16) float sm[];
    float* Qs  = sm;                        // 64 x 132
    float* KVs = Qs + 64 * QST;             // 64 x 136 (K, then V)
    float* Ps  = KVs + 64 * KST;            // 64 x 68
    float* wmx = Ps + 64 * PST;             // [2][64]
    float* wsp = wmx + 128;                 // [2][64]
    float* wsx = wsp + 128;                 // [2][64]

    int tid  = threadIdx.x;
    int lane = tid & 31, wid = tid >> 5;
    int gid  = lane >> 2, tig = lane & 3;
    int rg   = wid >> 1, half = wid & 1;
    int Q0 = blockIdx.x * 64;
    int b  = blockIdx.y;
    const float* Qb = g_Q + ((size_t)b * T_ + Q0) * HD;
    const float* Kb = g_K + (size_t)b * TKP * HD;
    const float* Vb = g_V + (size_t)b * TKP * HD;

    // stage Q (scaled + tf32)
#pragma unroll
    for (int it = 0; it < 8; it++) {
        int f = it * 256 + tid;
        int r = f >> 5, d4 = f & 31;
        float4 v = *(const float4*)(Qb + (size_t)r * HD + d4 * 4);
        v.x *= SCALE_INV; v.y *= SCALE_INV; v.z *= SCALE_INV; v.w *= SCALE_INV;
        *(float4*)(Qs + r * QST + d4 * 4) = f2tf4(v);
    }

    int r0 = rg * 16 + gid, r1 = r0 + 8;
    int kmax0 = (Q0 + r0) >> 2, kmax1 = (Q0 + r1) >> 2;
    int bt = Q0 >> 8;                       // boundary tile index
    int n0 = half * 32;                     // S-phase key base
    int cc = half * 64;                     // PV-phase col base

    float m0r = -1e30f, m1r = -1e30f;
    float sp0 = 0.f, sp1 = 0.f, sx0 = 0.f, sx1 = 0.f;
    float Om[8][4], Ox[8][4];
#pragma unroll
    for (int nf = 0; nf < 8; nf++)
#pragma unroll
        for (int j = 0; j < 4; j++) { Om[nf][j] = 0.f; Ox[nf][j] = 0.f; }

    for (int kt = 0; kt < 16; kt++) {
        __syncthreads();                                    // (A) KVs/Ps free
        // stage K tile
#pragma unroll
        for (int it = 0; it < 8; it++) {
            int f = it * 256 + tid;
            int kr = f >> 5, d4 = f & 31;
            float4 v = *(const float4*)(Kb + (size_t)(kt * 64 + kr) * HD + d4 * 4);
            *(float4*)(KVs + kr * KST + d4 * 4) = f2tf4(v);
        }
        __syncthreads();                                    // (B)

        // S = Q K^T for this tile (warp: 16 rows x 32 keys)
        float c[4][4];
#pragma unroll
        for (int nf = 0; nf < 4; nf++)
#pragma unroll
            for (int j = 0; j < 4; j++) c[nf][j] = 0.f;
#pragma unroll
        for (int ks = 0; ks < 16; ks++) {
            int k0 = ks * 8;
            float a0 = Qs[r0 * QST + k0 + tig];
            float a1 = Qs[r1 * QST + k0 + tig];
            float a2 = Qs[r0 * QST + k0 + tig + 4];
            float a3 = Qs[r1 * QST + k0 + tig + 4];
#pragma unroll
            for (int nf = 0; nf < 4; nf++) {
                const float* kp = KVs + (n0 + nf * 8 + gid) * KST + k0 + tig;
                mma8(c[nf], a0, a1, a2, a3, kp[0], kp[4]);
            }
        }
        // tile row-max
        float t0 = -1e30f, t1 = -1e30f;
#pragma unroll
        for (int nf = 0; nf < 4; nf++) {
            t0 = fmaxf(t0, fmaxf(c[nf][0], c[nf][1]));
            t1 = fmaxf(t1, fmaxf(c[nf][2], c[nf][3]));
        }
        t0 = fmaxf(t0, __shfl_xor_sync(0xffffffffu, t0, 1));
        t0 = fmaxf(t0, __shfl_xor_sync(0xffffffffu, t0, 2));
        t1 = fmaxf(t1, __shfl_xor_sync(0xffffffffu, t1, 1));
        t1 = fmaxf(t1, __shfl_xor_sync(0xffffffffu, t1, 2));
        if (tig == 0) { wmx[half * 64 + r0] = t0; wmx[half * 64 + r1] = t1; }
        __syncthreads();                                    // (C) S done, wmx ready

        float mn0 = fmaxf(m0r, fmaxf(wmx[r0], wmx[64 + r0]));
        float mn1 = fmaxf(m1r, fmaxf(wmx[r1], wmx[64 + r1]));
        float sc0 = __expf(m0r - mn0);
        float sc1 = __expf(m1r - mn1);
        m0r = mn0; m1r = mn1;
        sp0 *= sc0; sx0 *= sc0; sp1 *= sc1; sx1 *= sc1;
#pragma unroll
        for (int nf = 0; nf < 8; nf++) {
            Om[nf][0] *= sc0; Om[nf][1] *= sc0; Om[nf][2] *= sc1; Om[nf][3] *= sc1;
            Ox[nf][0] *= sc0; Ox[nf][1] *= sc0; Ox[nf][2] *= sc1; Ox[nf][3] *= sc1;
        }
        // exp, write P (tf32), local sums
        float lp0 = 0.f, lx0 = 0.f, lp1 = 0.f, lx1 = 0.f;
#pragma unroll
        for (int nf = 0; nf < 4; nf++) {
            int kl = n0 + nf * 8 + 2 * tig;
            int kg = kt * 64 + kl;
            float p0 = f2tf(__expf(c[nf][0] - mn0));
            float p1 = f2tf(__expf(c[nf][1] - mn0));
            float p2 = f2tf(__expf(c[nf][2] - mn1));
            float p3 = f2tf(__expf(c[nf][3] - mn1));
            *(float2*)(Ps + r0 * PST + kl) = make_float2(p0, p1);
            *(float2*)(Ps + r1 * PST + kl) = make_float2(p2, p3);
            if (kg     <= kmax0) lp0 += p0; else lx0 += p0;
            if (kg + 1 <= kmax0) lp0 += p1; else lx0 += p1;
            if (kg     <= kmax1) lp1 += p2; else lx1 += p2;
            if (kg + 1 <= kmax1) lp1 += p3; else lx1 += p3;
        }
        lp0 += __shfl_xor_sync(0xffffffffu, lp0, 1); lp0 += __shfl_xor_sync(0xffffffffu, lp0, 2);
        lx0 += __shfl_xor_sync(0xffffffffu, lx0, 1); lx0 += __shfl_xor_sync(0xffffffffu, lx0, 2);
        lp1 += __shfl_xor_sync(0xffffffffu, lp1, 1); lp1 += __shfl_xor_sync(0xffffffffu, lp1, 2);
        lx1 += __shfl_xor_sync(0xffffffffu, lx1, 1); lx1 += __shfl_xor_sync(0xffffffffu, lx1, 2);
        if (tig == 0) {
            wsp[half * 64 + r0] = lp0; wsp[half * 64 + r1] = lp1;
            wsx[half * 64 + r0] = lx0; wsx[half * 64 + r1] = lx1;
        }
        // stage V tile (K reads finished before (C))
#pragma unroll
        for (int it = 0; it < 8; it++) {
            int f = it * 256 + tid;
            int kr = f >> 5, d4 = f & 31;
            float4 v = *(const float4*)(Vb + (size_t)(kt * 64 + kr) * HD + d4 * 4);
            *(float4*)(KVs + kr * KST + d4 * 4) = f2tf4(v);
        }
        __syncthreads();                                    // (D) P, V, sums ready

        sp0 += wsp[r0] + wsp[64 + r0];
        sp1 += wsp[r1] + wsp[64 + r1];
        sx0 += wsx[r0] + wsx[64 + r0];
        sx1 += wsx[r1] + wsx[64 + r1];

        // PV mma into Om (prefix) / Ox (extra); boundary tile does both with masks
        if (kt < bt) {
#pragma unroll
            for (int ks = 0; ks < 8; ks++) {
                int k0 = ks * 8;
                float a0 = Ps[r0 * PST + k0 + tig];
                float a1 = Ps[r1 * PST + k0 + tig];
                float a2 = Ps[r0 * PST + k0 + tig + 4];
                float a3 = Ps[r1 * PST + k0 + tig + 4];
#pragma unroll
                for (int nf = 0; nf < 8; nf++) {
                    const float* vp = KVs + (k0 + tig) * KST + cc + nf * 8 + gid;
                    mma8(Om[nf], a0, a1, a2, a3, vp[0], vp[4 * KST]);
                }
            }
        } else if (kt > bt) {
#pragma unroll
            for (int ks = 0; ks < 8; ks++) {
                int k0 = ks * 8;
                float a0 = Ps[r0 * PST + k0 + tig];
                float a1 = Ps[r1 * PST + k0 + tig];
                float a2 = Ps[r0 * PST + k0 + tig + 4];
                float a3 = Ps[r1 * PST + k0 + tig + 4];
#pragma unroll
                for (int nf = 0; nf < 8; nf++) {
                    const float* vp = KVs + (k0 + tig) * KST + cc + nf * 8 + gid;
                    mma8(Ox[nf], a0, a1, a2, a3, vp[0], vp[4 * KST]);
                }
            }
        } else {
#pragma unroll
            for (int ks = 0; ks < 8; ks++) {
                int k0 = ks * 8;
                int kgA = kt * 64 + k0 + tig;
                int kgB = kgA + 4;
                float a0 = Ps[r0 * PST + k0 + tig];
                float a1 = Ps[r1 * PST + k0 + tig];
                float a2 = Ps[r0 * PST + k0 + tig + 4];
                float a3 = Ps[r1 * PST + k0 + tig + 4];
                float m0_ = (kgA <= kmax0) ? a0 : 0.f;
                float m1_ = (kgA <= kmax1) ? a1 : 0.f;
                float m2_ = (kgB <= kmax0) ? a2 : 0.f;
                float m3_ = (kgB <= kmax1) ? a3 : 0.f;
                float x0_ = a0 - m0_, x1_ = a1 - m1_, x2_ = a2 - m2_, x3_ = a3 - m3_;
#pragma unroll
                for (int nf = 0; nf < 8; nf++) {
                    const float* vp = KVs + (k0 + tig) * KST + cc + nf * 8 + gid;
                    float b0 = vp[0], b1 = vp[4 * KST];
                    mma8(Om[nf], m0_, m1_, m2_, m3_, b0, b1);
                    mma8(Ox[nf], x0_, x1_, x2_, x3_, b0, b1);
                }
            }
        }
    }

    // epilogue
    float alpha = 1.f / (1.f + __expf(-__ldg(alpha_p)));
    float wp0 = alpha / sp0;
    float wp1 = alpha / sp1;
    float wu0 = (1.f - alpha) / (sp0 + sx0);
    float wu1 = (1.f - alpha) / (sp1 + sx1);

    int qg0 = Q0 + r0, qg1 = Q0 + r1;
    float* O0 = Out + ((size_t)b * T_ + qg0) * HD;
    float* O1 = Out + ((size_t)b * T_ + qg1) * HD;
    float* U0 = g_U + ((size_t)b * T_ + (T_ - 1 - qg0)) * HD;
    float* U1 = g_U + ((size_t)b * T_ + (T_ - 1 - qg1)) * HD;
#pragma unroll
    for (int nf = 0; nf < 8; nf++) {
        int col = cc + nf * 8 + 2 * tig;
        *(float2*)(O0 + col) = make_float2(Om[nf][0] * wp0, Om[nf][1] * wp0);
        *(float2*)(O1 + col) = make_float2(Om[nf][2] * wp1, Om[nf][3] * wp1);
        *(float2*)(U0 + col) = make_float2((Om[nf][0] + Ox[nf][0]) * wu0,
                                           (Om[nf][1] + Ox[nf][1]) * wu0);
        *(float2*)(U1 + col) = make_float2((Om[nf][2] + Ox[nf][2]) * wu1,
                                           (Om[nf][3] + Ox[nf][3]) * wu1);
    }
}

// ---------------- combine ----------------
__global__ void combine_k(float* __restrict__ out) {
    int f = blockIdx.x * 256 + threadIdx.x;
    float4* o = (float4*)out;
    const float4* u = (const float4*)g_U;
    float4 a = o[f], bv = u[f];
    a.x += bv.x; a.y += bv.y; a.z += bv.z; a.w += bv.w;
    o[f] = a;
}

// ---------------- launch ----------------
extern "C" void kernel_launch(void* const* d_in, const int* in_sizes, int n_in,
                              void* d_out, int out_size) {
    const float* x  = (const float*)d_in[0];
    const float* Wq = (const float*)d_in[1];
    const float* Wk = (const float*)d_in[2];
    const float* Wv = (const float*)d_in[3];
    const float* fa = (const float*)d_in[9];
    float* out = (float*)d_out;

    const int ATTN_SMEM = (64 * QST + 64 * KST + 64 * PST + 3 * 128) * 4;  // 87552 B
    cudaFuncSetAttribute(attn_k, cudaFuncAttributeMaxDynamicSharedMemorySize, ATTN_SMEM);

    theta_k<<<1, 64>>>();
    rope_table_k<<<T_, 64>>>();
    pool_x_k<<<(B_ * TKP * (DM / 4)) / 256, 256>>>(x);
    proj_k<<<192, 256>>>(x, Wq, Wk, Wv);
    rope2_k<<<(B_ * T_ * 16) / 256, 256>>>(0);
    rope2_k<<<(B_ * TKP * 16) / 256, 256>>>(1);
    attn_k<<<dim3(T_ / 64, B_), 256, ATTN_SMEM>>>(fa, out);
    combine_k<<<(B_ * T_ * HD / 4) / 256, 256>>>(out);
}

// round 4
// speedup vs baseline: 3.5586x; 1.1939x over previous
#include <cuda_runtime.h>
#include <cstdint>

#define B_  4
#define T_  4096
#define TKP 1024
#define DM  1024
#define HD  128
#define SCALE_INV 0.08838834764831845f   // 1/sqrt(128)

// ---------------- static device scratch ----------------
__device__ float  g_xp[B_ * TKP * DM];
__device__ float  g_Q [B_ * T_  * HD];
__device__ float  g_K [B_ * TKP * HD];
__device__ float  g_V [B_ * TKP * HD];
__device__ float  g_cos[T_ * 64];
__device__ float  g_sin[T_ * 64];
__device__ double g_theta[64];

// ---------------- helpers ----------------
__device__ __forceinline__ unsigned f2t(float x) {
    unsigned r; asm("cvt.rna.tf32.f32 %0, %1;" : "=r"(r) : "f"(x)); return r;
}
__device__ __forceinline__ float f2tf(float x) { return __uint_as_float(f2t(x)); }
__device__ __forceinline__ float4 f2tf4(float4 v) {
    return make_float4(f2tf(v.x), f2tf(v.y), f2tf(v.z), f2tf(v.w));
}
__device__ __forceinline__ void mma8(float* d,
                                     float a0, float a1, float a2, float a3,
                                     float b0, float b1) {
    asm volatile("mma.sync.aligned.m16n8k8.row.col.f32.tf32.tf32.f32 "
                 "{%0,%1,%2,%3},{%4,%5,%6,%7},{%8,%9},{%0,%1,%2,%3};"
                 : "+f"(d[0]), "+f"(d[1]), "+f"(d[2]), "+f"(d[3])
                 : "r"(__float_as_uint(a0)), "r"(__float_as_uint(a1)),
                   "r"(__float_as_uint(a2)), "r"(__float_as_uint(a3)),
                   "r"(__float_as_uint(b0)), "r"(__float_as_uint(b1)));
}
__device__ __forceinline__ void cpa16(uint32_t dst, const void* src) {
    asm volatile("cp.async.cg.shared.global [%0], [%1], 16;" :: "r"(dst), "l"(src));
}

// ---------------- RoPE tables ----------------
__global__ void theta_k() {
    int i = threadIdx.x;
    g_theta[i] = exp(((double)(-i) / 64.0) * log(10000.0));
}
__global__ void rope_table_k() {
    int t = blockIdx.x, i = threadIdx.x;
    float thf = (float)g_theta[i];
    float arg = (float)t * thf;          // fp32 product, matching reference
    const double TWO_PI  = 6.283185307179586476925286766559;
    const double INV2PI  = 0.15915494309189533576888376337251;
    double da = (double)arg;
    double k  = rint(da * INV2PI);
    float  r  = (float)(da - k * TWO_PI);
    g_cos[t * 64 + i] = cosf(r);
    g_sin[t * 64 + i] = sinf(r);
}

// ---------------- stride-4 mean pool ----------------
__global__ void pool_x_k(const float* __restrict__ x) {
    int f   = blockIdx.x * 256 + threadIdx.x;
    int c4  = f & 255;
    int row = f >> 8;
    int b   = row >> 10, tp = row & 1023;
    const float4* xi = (const float4*)x;
    size_t base = ((size_t)b * T_ + 4 * tp) * (DM / 4) + c4;
    float4 a = xi[base];
    float4 b2 = xi[base + (DM / 4)];
    float4 c = xi[base + 2 * (DM / 4)];
    float4 d = xi[base + 3 * (DM / 4)];
    float4 o;
    o.x = (a.x + b2.x + c.x + d.x) * 0.25f;
    o.y = (a.y + b2.y + c.y + d.y) * 0.25f;
    o.z = (a.z + b2.z + c.z + d.z) * 0.25f;
    o.w = (a.w + b2.w + c.w + d.w) * 0.25f;
    ((float4*)g_xp)[(size_t)row * (DM / 4) + c4] = o;
}

// ---------------- projection GEMM v3: cp.async double-buffer, BK=32, 2-term TF32 ----
// grid 192: [0,128) Q = x@Wq; [128,160) K = xp@Wk; [160,192) V = xp@Wv
#define AST 36      // A smem row stride (floats), BK=32 + pad
#define BST 136     // B smem row stride
#define ABUF (128 * AST)
#define BBUF (32 * BST)
__global__ void __launch_bounds__(256, 2) proj_k(
    const float* __restrict__ x,
    const float* __restrict__ Wq, const float* __restrict__ Wk, const float* __restrict__ Wv)
{
    extern __shared__ __align__(16) float psm[];
    float* As = psm;                 // [2][128][AST]
    float* Bs = psm + 2 * ABUF;      // [2][32][BST]

    int bid = blockIdx.x;
    const float* A; const float* Wm; float* Cm; int m0;
    if (bid < 128)      { A = x;    Wm = Wq; Cm = g_Q; m0 = bid * 128; }
    else if (bid < 160) { A = g_xp; Wm = Wk; Cm = g_K; m0 = (bid - 128) * 128; }
    else                { A = g_xp; Wm = Wv; Cm = g_V; m0 = (bid - 160) * 128; }

    int tid  = threadIdx.x;
    int lane = tid & 31, wid = tid >> 5;
    int gid  = lane >> 2, tig = lane & 3;
    int wm = wid >> 1, wn = wid & 1;

    uint32_t sA = (uint32_t)__cvta_generic_to_shared(As);
    uint32_t sB = (uint32_t)__cvta_generic_to_shared(Bs);

    // precomputed per-thread staging indices
    int ar = tid >> 3, ac = tid & 7;     // A: rows step 32 per iter (r = ar + 32*it)
    int br = tid >> 5, bc = tid & 31;    // B: rows step 8 per iter

    auto stage = [&](int kb, int buf) {
#pragma unroll
        for (int it = 0; it < 4; it++) {
            int r = ar + it * 32;
            cpa16(sA + (uint32_t)((buf * ABUF + r * AST + ac * 4) * 4),
                  A + (size_t)(m0 + r) * DM + kb * 32 + ac * 4);
        }
#pragma unroll
        for (int it = 0; it < 4; it++) {
            int r = br + it * 8;
            cpa16(sB + (uint32_t)((buf * BBUF + r * BST + bc * 4) * 4),
                  Wm + (size_t)(kb * 32 + r) * HD + bc * 4);
        }
        asm volatile("cp.async.commit_group;");
    };

    float C[2][8][4];
#pragma unroll
    for (int mf = 0; mf < 2; mf++)
#pragma unroll
        for (int nf = 0; nf < 8; nf++)
#pragma unroll
            for (int j = 0; j < 4; j++) C[mf][nf][j] = 0.f;

    stage(0, 0);
    stage(1, 1);

    for (int kb = 0; kb < 32; kb++) {
        if (kb < 30) { asm volatile("cp.async.wait_group 1;"); }
        else         { asm volatile("cp.async.wait_group 0;"); }
        __syncthreads();
        const float* Ab = As + (kb & 1) * ABUF;
        const float* Bb = Bs + (kb & 1) * BBUF;
#pragma unroll
        for (int ks = 0; ks < 4; ks++) {
            int k0 = ks * 8;
            float ah[2][4], al[2][4];
#pragma unroll
            for (int mf = 0; mf < 2; mf++) {
                int mb = wm * 32 + mf * 16;
                float r0 = Ab[(mb + gid)     * AST + k0 + tig];
                float r1 = Ab[(mb + gid + 8) * AST + k0 + tig];
                float r2 = Ab[(mb + gid)     * AST + k0 + tig + 4];
                float r3 = Ab[(mb + gid + 8) * AST + k0 + tig + 4];
                ah[mf][0] = f2tf(r0); al[mf][0] = f2tf(r0 - ah[mf][0]);
                ah[mf][1] = f2tf(r1); al[mf][1] = f2tf(r1 - ah[mf][1]);
                ah[mf][2] = f2tf(r2); al[mf][2] = f2tf(r2 - ah[mf][2]);
                ah[mf][3] = f2tf(r3); al[mf][3] = f2tf(r3 - ah[mf][3]);
            }
#pragma unroll
            for (int nf = 0; nf < 8; nf++) {
                int nb = wn * 64 + nf * 8 + gid;
                float b0 = f2tf(Bb[(k0 + tig)     * BST + nb]);
                float b1 = f2tf(Bb[(k0 + tig + 4) * BST + nb]);
#pragma unroll
                for (int mf = 0; mf < 2; mf++) {
                    mma8(C[mf][nf], ah[mf][0], ah[mf][1], ah[mf][2], ah[mf][3], b0, b1);
                    mma8(C[mf][nf], al[mf][0], al[mf][1], al[mf][2], al[mf][3], b0, b1);
                }
            }
        }
        __syncthreads();
        if (kb + 2 < 32) stage(kb + 2, kb & 1);
    }

#pragma unroll
    for (int mf = 0; mf < 2; mf++) {
        int r0 = m0 + wm * 32 + mf * 16 + gid;
#pragma unroll
        for (int nf = 0; nf < 8; nf++) {
            int col = wn * 64 + nf * 8 + 2 * tig;
            *(float2*)(Cm + (size_t)r0 * HD + col)       = make_float2(C[mf][nf][0], C[mf][nf][1]);
            *(float2*)(Cm + (size_t)(r0 + 8) * HD + col) = make_float2(C[mf][nf][2], C[mf][nf][3]);
        }
    }
}

// ---------------- zero output ----------------
__global__ void zero_k(float* __restrict__ out) {
    ((float4*)out)[blockIdx.x * 256 + threadIdx.x] = make_float4(0.f, 0.f, 0.f, 0.f);
}

// ---------------- flash attention: fused RoPE staging, dual softmax, atomic epilogue ----
#define QST 132
#define KST 136
#define PST 68
__global__ void __launch_bounds__(256, 2) attn_k(const float* __restrict__ alpha_p,
                                                 float* __restrict__ Out)
{
    extern __shared__ __align__(16) float sm[];
    float* Qs  = sm;                        // 64 x 132
    float* KVs = Qs + 64 * QST;             // 64 x 136
    float* Ps  = KVs + 64 * KST;            // 64 x 68
    float* wmx = Ps + 64 * PST;             // [2][64]
    float* wsp = wmx + 128;
    float* wsx = wsp + 128;

    int tid  = threadIdx.x;
    int lane = tid & 31, wid = tid >> 5;
    int gid  = lane >> 2, tig = lane & 3;
    int rg   = wid >> 1, half = wid & 1;
    int Q0 = blockIdx.x * 64;
    int b  = blockIdx.y;
    const float* Qb = g_Q + ((size_t)b * T_ + Q0) * HD;
    const float* Kb = g_K + (size_t)b * TKP * HD;
    const float* Vb = g_V + (size_t)b * TKP * HD;

    // stage Q with fused RoPE (scaled + tf32)
#pragma unroll
    for (int it = 0; it < 4; it++) {
        int f = it * 256 + tid;
        int r = f >> 4, i4 = f & 15;
        int pos = Q0 + r;
        const float* p = Qb + (size_t)r * HD + i4 * 4;
        float4 x1 = *(const float4*)(p);
        float4 x2 = *(const float4*)(p + 64);
        float4 c  = *(const float4*)(g_cos + pos * 64 + i4 * 4);
        float4 s  = *(const float4*)(g_sin + pos * 64 + i4 * 4);
        float4 o1 = make_float4((x1.x * c.x - x2.x * s.x) * SCALE_INV,
                                (x1.y * c.y - x2.y * s.y) * SCALE_INV,
                                (x1.z * c.z - x2.z * s.z) * SCALE_INV,
                                (x1.w * c.w - x2.w * s.w) * SCALE_INV);
        float4 o2 = make_float4((x2.x * c.x + x1.x * s.x) * SCALE_INV,
                                (x2.y * c.y + x1.y * s.y) * SCALE_INV,
                                (x2.z * c.z + x1.z * s.z) * SCALE_INV,
                                (x2.w * c.w + x1.w * s.w) * SCALE_INV);
        *(float4*)(Qs + r * QST + i4 * 4)      = f2tf4(o1);
        *(float4*)(Qs + r * QST + 64 + i4 * 4) = f2tf4(o2);
    }

    int r0 = rg * 16 + gid, r1 = r0 + 8;
    int kmax0 = (Q0 + r0) >> 2, kmax1 = (Q0 + r1) >> 2;
    int bt = Q0 >> 8;
    int n0 = half * 32;
    int cc = half * 64;

    float m0r = -1e30f, m1r = -1e30f;
    float sp0 = 0.f, sp1 = 0.f, sx0 = 0.f, sx1 = 0.f;
    float Om[8][4], Ox[8][4];
#pragma unroll
    for (int nf = 0; nf < 8; nf++)
#pragma unroll
        for (int j = 0; j < 4; j++) { Om[nf][j] = 0.f; Ox[nf][j] = 0.f; }

    for (int kt = 0; kt < 16; kt++) {
        __syncthreads();                                    // (A)
        // stage K tile with fused RoPE (tf32)
#pragma unroll
        for (int it = 0; it < 4; it++) {
            int f = it * 256 + tid;
            int kr = f >> 4, i4 = f & 15;
            int pos = kt * 64 + kr;
            const float* p = Kb + (size_t)pos * HD + i4 * 4;
            float4 x1 = *(const float4*)(p);
            float4 x2 = *(const float4*)(p + 64);
            float4 c  = *(const float4*)(g_cos + pos * 64 + i4 * 4);
            float4 s  = *(const float4*)(g_sin + pos * 64 + i4 * 4);
            float4 o1 = make_float4(x1.x * c.x - x2.x * s.x, x1.y * c.y - x2.y * s.y,
                                    x1.z * c.z - x2.z * s.z, x1.w * c.w - x2.w * s.w);
            float4 o2 = make_float4(x2.x * c.x + x1.x * s.x, x2.y * c.y + x1.y * s.y,
                                    x2.z * c.z + x1.z * s.z, x2.w * c.w + x1.w * s.w);
            *(float4*)(KVs + kr * KST + i4 * 4)      = f2tf4(o1);
            *(float4*)(KVs + kr * KST + 64 + i4 * 4) = f2tf4(o2);
        }
        __syncthreads();                                    // (B)

        // S = Q K^T (warp: 16 rows x 32 keys)
        float c[4][4];
#pragma unroll
        for (int nf = 0; nf < 4; nf++)
#pragma unroll
            for (int j = 0; j < 4; j++) c[nf][j] = 0.f;
#pragma unroll
        for (int ks = 0; ks < 16; ks++) {
            int k0 = ks * 8;
            float a0 = Qs[r0 * QST + k0 + tig];
            float a1 = Qs[r1 * QST + k0 + tig];
            float a2 = Qs[r0 * QST + k0 + tig + 4];
            float a3 = Qs[r1 * QST + k0 + tig + 4];
#pragma unroll
            for (int nf = 0; nf < 4; nf++) {
                const float* kp = KVs + (n0 + nf * 8 + gid) * KST + k0 + tig;
                mma8(c[nf], a0, a1, a2, a3, kp[0], kp[4]);
            }
        }
        float t0 = -1e30f, t1 = -1e30f;
#pragma unroll
        for (int nf = 0; nf < 4; nf++) {
            t0 = fmaxf(t0, fmaxf(c[nf][0], c[nf][1]));
            t1 = fmaxf(t1, fmaxf(c[nf][2], c[nf][3]));
        }
        t0 = fmaxf(t0, __shfl_xor_sync(0xffffffffu, t0, 1));
        t0 = fmaxf(t0, __shfl_xor_sync(0xffffffffu, t0, 2));
        t1 = fmaxf(t1, __shfl_xor_sync(0xffffffffu, t1, 1));
        t1 = fmaxf(t1, __shfl_xor_sync(0xffffffffu, t1, 2));
        if (tig == 0) { wmx[half * 64 + r0] = t0; wmx[half * 64 + r1] = t1; }
        __syncthreads();                                    // (C)

        float mn0 = fmaxf(m0r, fmaxf(wmx[r0], wmx[64 + r0]));
        float mn1 = fmaxf(m1r, fmaxf(wmx[r1], wmx[64 + r1]));
        float sc0 = __expf(m0r - mn0);
        float sc1 = __expf(m1r - mn1);
        m0r = mn0; m1r = mn1;
        sp0 *= sc0; sx0 *= sc0; sp1 *= sc1; sx1 *= sc1;
#pragma unroll
        for (int nf = 0; nf < 8; nf++) {
            Om[nf][0] *= sc0; Om[nf][1] *= sc0; Om[nf][2] *= sc1; Om[nf][3] *= sc1;
            Ox[nf][0] *= sc0; Ox[nf][1] *= sc0; Ox[nf][2] *= sc1; Ox[nf][3] *= sc1;
        }
        float lp0 = 0.f, lx0 = 0.f, lp1 = 0.f, lx1 = 0.f;
#pragma unroll
        for (int nf = 0; nf < 4; nf++) {
            int kl = n0 + nf * 8 + 2 * tig;
            int kg = kt * 64 + kl;
            float p0 = f2tf(__expf(c[nf][0] - mn0));
            float p1 = f2tf(__expf(c[nf][1] - mn0));
            float p2 = f2tf(__expf(c[nf][2] - mn1));
            float p3 = f2tf(__expf(c[nf][3] - mn1));
            *(float2*)(Ps + r0 * PST + kl) = make_float2(p0, p1);
            *(float2*)(Ps + r1 * PST + kl) = make_float2(p2, p3);
            if (kg     <= kmax0) lp0 += p0; else lx0 += p0;
            if (kg + 1 <= kmax0) lp0 += p1; else lx0 += p1;
            if (kg     <= kmax1) lp1 += p2; else lx1 += p2;
            if (kg + 1 <= kmax1) lp1 += p3; else lx1 += p3;
        }
        lp0 += __shfl_xor_sync(0xffffffffu, lp0, 1); lp0 += __shfl_xor_sync(0xffffffffu, lp0, 2);
        lx0 += __shfl_xor_sync(0xffffffffu, lx0, 1); lx0 += __shfl_xor_sync(0xffffffffu, lx0, 2);
        lp1 += __shfl_xor_sync(0xffffffffu, lp1, 1); lp1 += __shfl_xor_sync(0xffffffffu, lp1, 2);
        lx1 += __shfl_xor_sync(0xffffffffu, lx1, 1); lx1 += __shfl_xor_sync(0xffffffffu, lx1, 2);
        if (tig == 0) {
            wsp[half * 64 + r0] = lp0; wsp[half * 64 + r1] = lp1;
            wsx[half * 64 + r0] = lx0; wsx[half * 64 + r1] = lx1;
        }
        // stage V tile (no rope)
#pragma unroll
        for (int it = 0; it < 8; it++) {
            int f = it * 256 + tid;
            int kr = f >> 5, d4 = f & 31;
            float4 v = *(const float4*)(Vb + (size_t)(kt * 64 + kr) * HD + d4 * 4);
            *(float4*)(KVs + kr * KST + d4 * 4) = f2tf4(v);
        }
        __syncthreads();                                    // (D)

        sp0 += wsp[r0] + wsp[64 + r0];
        sp1 += wsp[r1] + wsp[64 + r1];
        sx0 += wsx[r0] + wsx[64 + r0];
        sx1 += wsx[r1] + wsx[64 + r1];

        if (kt < bt) {
#pragma unroll
            for (int ks = 0; ks < 8; ks++) {
                int k0 = ks * 8;
                float a0 = Ps[r0 * PST + k0 + tig];
                float a1 = Ps[r1 * PST + k0 + tig];
                float a2 = Ps[r0 * PST + k0 + tig + 4];
                float a3 = Ps[r1 * PST + k0 + tig + 4];
#pragma unroll
                for (int nf = 0; nf < 8; nf++) {
                    const float* vp = KVs + (k0 + tig) * KST + cc + nf * 8 + gid;
                    mma8(Om[nf], a0, a1, a2, a3, vp[0], vp[4 * KST]);
                }
            }
        } else if (kt > bt) {
#pragma unroll
            for (int ks = 0; ks < 8; ks++) {
                int k0 = ks * 8;
                float a0 = Ps[r0 * PST + k0 + tig];
                float a1 = Ps[r1 * PST + k0 + tig];
                float a2 = Ps[r0 * PST + k0 + tig + 4];
                float a3 = Ps[r1 * PST + k0 + tig + 4];
#pragma unroll
                for (int nf = 0; nf < 8; nf++) {
                    const float* vp = KVs + (k0 + tig) * KST + cc + nf * 8 + gid;
                    mma8(Ox[nf], a0, a1, a2, a3, vp[0], vp[4 * KST]);
                }
            }
        } else {
#pragma unroll
            for (int ks = 0; ks < 8; ks++) {
                int k0 = ks * 8;
                int kgA = kt * 64 + k0 + tig;
                int kgB = kgA + 4;
                float a0 = Ps[r0 * PST + k0 + tig];
                float a1 = Ps[r1 * PST + k0 + tig];
                float a2 = Ps[r0 * PST + k0 + tig + 4];
                float a3 = Ps[r1 * PST + k0 + tig + 4];
                float m0_ = (kgA <= kmax0) ? a0 : 0.f;
                float m1_ = (kgA <= kmax1) ? a1 : 0.f;
                float m2_ = (kgB <= kmax0) ? a2 : 0.f;
                float m3_ = (kgB <= kmax1) ? a3 : 0.f;
                float x0_ = a0 - m0_, x1_ = a1 - m1_, x2_ = a2 - m2_, x3_ = a3 - m3_;
#pragma unroll
                for (int nf = 0; nf < 8; nf++) {
                    const float* vp = KVs + (k0 + tig) * KST + cc + nf * 8 + gid;
                    float b0 = vp[0], b1 = vp[4 * KST];
                    mma8(Om[nf], m0_, m1_, m2_, m3_, b0, b1);
                    mma8(Ox[nf], x0_, x1_, x2_, x3_, b0, b1);
                }
            }
        }
    }

    // epilogue: atomic adds into zeroed Out (2 commutative adds per element -> deterministic)
    float alpha = 1.f / (1.f + __expf(-__ldg(alpha_p)));
    float wp0 = alpha / sp0;
    float wp1 = alpha / sp1;
    float wu0 = (1.f - alpha) / (sp0 + sx0);
    float wu1 = (1.f - alpha) / (sp1 + sx1);

    int qg0 = Q0 + r0, qg1 = Q0 + r1;
    float* O0 = Out + ((size_t)b * T_ + qg0) * HD;
    float* O1 = Out + ((size_t)b * T_ + qg1) * HD;
    float* U0 = Out + ((size_t)b * T_ + (T_ - 1 - qg0)) * HD;
    float* U1 = Out + ((size_t)b * T_ + (T_ - 1 - qg1)) * HD;
#pragma unroll
    for (int nf = 0; nf < 8; nf++) {
        int col = cc + nf * 8 + 2 * tig;
        atomicAdd(O0 + col,     Om[nf][0] * wp0);
        atomicAdd(O0 + col + 1, Om[nf][1] * wp0);
        atomicAdd(O1 + col,     Om[nf][2] * wp1);
        atomicAdd(O1 + col + 1, Om[nf][3] * wp1);
        atomicAdd(U0 + col,     (Om[nf][0] + Ox[nf][0]) * wu0);
        atomicAdd(U0 + col + 1, (Om[nf][1] + Ox[nf][1]) * wu0);
        atomicAdd(U1 + col,     (Om[nf][2] + Ox[nf][2]) * wu1);
        atomicAdd(U1 + col + 1, (Om[nf][3] + Ox[nf][3]) * wu1);
    }
}

// ---------------- launch ----------------
extern "C" void kernel_launch(void* const* d_in, const int* in_sizes, int n_in,
                              void* d_out, int out_size) {
    const float* x  = (const float*)d_in[0];
    const float* Wq = (const float*)d_in[1];
    const float* Wk = (const float*)d_in[2];
    const float* Wv = (const float*)d_in[3];
    const float* fa = (const float*)d_in[9];
    float* out = (float*)d_out;

    const int PROJ_SMEM = (2 * ABUF + 2 * BBUF) * 4;                        // 71680 B
    const int ATTN_SMEM = (64 * QST + 64 * KST + 64 * PST + 3 * 128) * 4;   // 87552 B
    cudaFuncSetAttribute(proj_k, cudaFuncAttributeMaxDynamicSharedMemorySize, PROJ_SMEM);
    cudaFuncSetAttribute(attn_k, cudaFuncAttributeMaxDynamicSharedMemorySize, ATTN_SMEM);

    theta_k<<<1, 64>>>();
    rope_table_k<<<T_, 64>>>();
    pool_x_k<<<(B_ * TKP * (DM / 4)) / 256, 256>>>(x);
    proj_k<<<192, 256, PROJ_SMEM>>>(x, Wq, Wk, Wv);
    zero_k<<<(B_ * T_ * HD / 4) / 256, 256>>>(out);
    attn_k<<<dim3(T_ / 64, B_), 256, ATTN_SMEM>>>(fa, out);
}

// round 6
// speedup vs baseline: 4.4972x; 1.2638x over previous
#include <cuda_runtime.h>
#include <cstdint>

#define B_  4
#define T_  4096
#define TKP 1024
#define DM  1024
#define HD  128
#define SCALE_INV 0.08838834764831845f   // 1/sqrt(128)

// ---------------- static device scratch ----------------
__device__ float  g_xp[B_ * TKP * DM];
__device__ float  g_Q [B_ * T_  * HD];
__device__ float  g_K [B_ * TKP * HD];
__device__ float  g_V [B_ * TKP * HD];
__device__ float  g_Wt[3 * DM * HD];     // tf32-rounded weights
__device__ float  g_cos[T_ * 64];
__device__ float  g_sin[T_ * 64];
__device__ double g_theta[64];

// ---------------- helpers ----------------
__device__ __forceinline__ unsigned f2t(float x) {
    unsigned r; asm("cvt.rna.tf32.f32 %0, %1;" : "=r"(r) : "f"(x)); return r;
}
__device__ __forceinline__ float f2tf(float x) { return __uint_as_float(f2t(x)); }
__device__ __forceinline__ float4 f2tf4(float4 v) {
    return make_float4(f2tf(v.x), f2tf(v.y), f2tf(v.z), f2tf(v.w));
}
__device__ __forceinline__ void mma8(float* d,
                                     float a0, float a1, float a2, float a3,
                                     float b0, float b1) {
    asm volatile("mma.sync.aligned.m16n8k8.row.col.f32.tf32.tf32.f32 "
                 "{%0,%1,%2,%3},{%4,%5,%6,%7},{%8,%9},{%0,%1,%2,%3};"
                 : "+f"(d[0]), "+f"(d[1]), "+f"(d[2]), "+f"(d[3])
                 : "r"(__float_as_uint(a0)), "r"(__float_as_uint(a1)),
                   "r"(__float_as_uint(a2)), "r"(__float_as_uint(a3)),
                   "r"(__float_as_uint(b0)), "r"(__float_as_uint(b1)));
}
__device__ __forceinline__ void cpa16(uint32_t dst, const void* src) {
    asm volatile("cp.async.cg.shared.global [%0], [%1], 16;" :: "r"(dst), "l"(src));
}

// ---------------- RoPE tables ----------------
__global__ void theta_k() {
    int i = threadIdx.x;
    g_theta[i] = exp(((double)(-i) / 64.0) * log(10000.0));
}
__global__ void rope_table_k() {
    int t = blockIdx.x, i = threadIdx.x;
    float thf = (float)g_theta[i];
    float arg = (float)t * thf;          // fp32 product, matching reference
    const double TWO_PI  = 6.283185307179586476925286766559;
    const double INV2PI  = 0.15915494309189533576888376337251;
    double da = (double)arg;
    double k  = rint(da * INV2PI);
    float  r  = (float)(da - k * TWO_PI);
    g_cos[t * 64 + i] = cosf(r);
    g_sin[t * 64 + i] = sinf(r);
}

// ---------------- pre-round weights to tf32 ----------------
__global__ void cvtW_k(const float* __restrict__ Wq, const float* __restrict__ Wk,
                       const float* __restrict__ Wv) {
    int f = blockIdx.x * 256 + threadIdx.x;     // float4 id, 3*32768 total
    int which = f >> 15;
    int idx = f & 32767;
    const float4* src = (const float4*)(which == 0 ? Wq : (which == 1 ? Wk : Wv));
    ((float4*)g_Wt)[which * 32768 + idx] = f2tf4(src[idx]);
}

// ---------------- stride-4 mean pool ----------------
__global__ void pool_x_k(const float* __restrict__ x) {
    int f   = blockIdx.x * 256 + threadIdx.x;
    int c4  = f & 255;
    int row = f >> 8;
    int b   = row >> 10, tp = row & 1023;
    const float4* xi = (const float4*)x;
    size_t base = ((size_t)b * T_ + 4 * tp) * (DM / 4) + c4;
    float4 a = xi[base];
    float4 b2 = xi[base + (DM / 4)];
    float4 c = xi[base + 2 * (DM / 4)];
    float4 d = xi[base + 3 * (DM / 4)];
    float4 o;
    o.x = (a.x + b2.x + c.x + d.x) * 0.25f;
    o.y = (a.y + b2.y + c.y + d.y) * 0.25f;
    o.z = (a.z + b2.z + c.z + d.z) * 0.25f;
    o.w = (a.w + b2.w + c.w + d.w) * 0.25f;
    ((float4*)g_xp)[(size_t)row * (DM / 4) + c4] = o;
}

// ---------------- projection GEMM: 1-term TF32, pre-rounded B, cp.async DB ----
#define AST 36
#define BST 136
#define ABUF (128 * AST)
#define BBUF (32 * BST)
__global__ void __launch_bounds__(256, 2) proj_k(const float* __restrict__ x) {
    extern __shared__ __align__(16) float psm[];
    float* As = psm;
    float* Bs = psm + 2 * ABUF;

    int bid = blockIdx.x;
    const float* A; const float* Wm; float* Cm; int m0; bool roundV = false;
    if (bid < 128)      { A = x;    Wm = g_Wt;                Cm = g_Q; m0 = bid * 128; }
    else if (bid < 160) { A = g_xp; Wm = g_Wt + DM * HD;      Cm = g_K; m0 = (bid - 128) * 128; }
    else                { A = g_xp; Wm = g_Wt + 2 * DM * HD;  Cm = g_V; m0 = (bid - 160) * 128; roundV = true; }

    int tid  = threadIdx.x;
    int lane = tid & 31, wid = tid >> 5;
    int gid  = lane >> 2, tig = lane & 3;
    int wm = wid >> 1, wn = wid & 1;

    uint32_t sA = (uint32_t)__cvta_generic_to_shared(As);
    uint32_t sB = (uint32_t)__cvta_generic_to_shared(Bs);
    int ar = tid >> 3, ac = tid & 7;
    int br = tid >> 5, bc = tid & 31;

    auto stage = [&](int kb, int buf) {
#pragma unroll
        for (int it = 0; it < 4; it++) {
            int r = ar + it * 32;
            cpa16(sA + (uint32_t)((buf * ABUF + r * AST + ac * 4) * 4),
                  A + (size_t)(m0 + r) * DM + kb * 32 + ac * 4);
        }
#pragma unroll
        for (int it = 0; it < 4; it++) {
            int r = br + it * 8;
            cpa16(sB + (uint32_t)((buf * BBUF + r * BST + bc * 4) * 4),
                  Wm + (size_t)(kb * 32 + r) * HD + bc * 4);
        }
        asm volatile("cp.async.commit_group;");
    };

    float C[2][8][4];
#pragma unroll
    for (int mf = 0; mf < 2; mf++)
#pragma unroll
        for (int nf = 0; nf < 8; nf++)
#pragma unroll
            for (int j = 0; j < 4; j++) C[mf][nf][j] = 0.f;

    stage(0, 0);
    stage(1, 1);

    for (int kb = 0; kb < 32; kb++) {
        if (kb < 30) { asm volatile("cp.async.wait_group 1;"); }
        else         { asm volatile("cp.async.wait_group 0;"); }
        __syncthreads();
        const float* Ab = As + (kb & 1) * ABUF;
        const float* Bb = Bs + (kb & 1) * BBUF;
#pragma unroll
        for (int ks = 0; ks < 4; ks++) {
            int k0 = ks * 8;
            float ah[2][4];
#pragma unroll
            for (int mf = 0; mf < 2; mf++) {
                int mb = wm * 32 + mf * 16;
                ah[mf][0] = f2tf(Ab[(mb + gid)     * AST + k0 + tig]);
                ah[mf][1] = f2tf(Ab[(mb + gid + 8) * AST + k0 + tig]);
                ah[mf][2] = f2tf(Ab[(mb + gid)     * AST + k0 + tig + 4]);
                ah[mf][3] = f2tf(Ab[(mb + gid + 8) * AST + k0 + tig + 4]);
            }
#pragma unroll
            for (int nf = 0; nf < 8; nf++) {
                int nb = wn * 64 + nf * 8 + gid;
                float b0 = Bb[(k0 + tig)     * BST + nb];
                float b1 = Bb[(k0 + tig + 4) * BST + nb];
#pragma unroll
                for (int mf = 0; mf < 2; mf++)
                    mma8(C[mf][nf], ah[mf][0], ah[mf][1], ah[mf][2], ah[mf][3], b0, b1);
            }
        }
        __syncthreads();
        if (kb + 2 < 32) stage(kb + 2, kb & 1);
    }

#pragma unroll
    for (int mf = 0; mf < 2; mf++) {
        int r0 = m0 + wm * 32 + mf * 16 + gid;
#pragma unroll
        for (int nf = 0; nf < 8; nf++) {
            int col = wn * 64 + nf * 8 + 2 * tig;
            float v0 = C[mf][nf][0], v1 = C[mf][nf][1];
            float v2 = C[mf][nf][2], v3 = C[mf][nf][3];
            if (roundV) { v0 = f2tf(v0); v1 = f2tf(v1); v2 = f2tf(v2); v3 = f2tf(v3); }
            *(float2*)(Cm + (size_t)r0 * HD + col)       = make_float2(v0, v1);
            *(float2*)(Cm + (size_t)(r0 + 8) * HD + col) = make_float2(v2, v3);
        }
    }
}

// ---------------- RoPE passes: Q (scale+round), K (round) ----------------
__global__ void ropeq_k() {
    int g = blockIdx.x * 256 + threadIdx.x;
    int i4 = g & 15;
    int row = g >> 4;
    int pos = row & (T_ - 1);
    float4 c  = *(float4*)(g_cos + pos * 64 + i4 * 4);
    float4 s  = *(float4*)(g_sin + pos * 64 + i4 * 4);
    float* p  = g_Q + (size_t)row * HD + i4 * 4;
    float4 x1 = *(float4*)(p);
    float4 x2 = *(float4*)(p + 64);
    float4 o1 = make_float4((x1.x * c.x - x2.x * s.x) * SCALE_INV,
                            (x1.y * c.y - x2.y * s.y) * SCALE_INV,
                            (x1.z * c.z - x2.z * s.z) * SCALE_INV,
                            (x1.w * c.w - x2.w * s.w) * SCALE_INV);
    float4 o2 = make_float4((x2.x * c.x + x1.x * s.x) * SCALE_INV,
                            (x2.y * c.y + x1.y * s.y) * SCALE_INV,
                            (x2.z * c.z + x1.z * s.z) * SCALE_INV,
                            (x2.w * c.w + x1.w * s.w) * SCALE_INV);
    *(float4*)(p)      = f2tf4(o1);
    *(float4*)(p + 64) = f2tf4(o2);
}
__global__ void ropek_k() {
    int g = blockIdx.x * 256 + threadIdx.x;
    int i4 = g & 15;
    int row = g >> 4;
    int pos = row & (TKP - 1);
    float4 c  = *(float4*)(g_cos + pos * 64 + i4 * 4);
    float4 s  = *(float4*)(g_sin + pos * 64 + i4 * 4);
    float* p  = g_K + (size_t)row * HD + i4 * 4;
    float4 x1 = *(float4*)(p);
    float4 x2 = *(float4*)(p + 64);
    float4 o1 = make_float4(x1.x * c.x - x2.x * s.x, x1.y * c.y - x2.y * s.y,
                            x1.z * c.z - x2.z * s.z, x1.w * c.w - x2.w * s.w);
    float4 o2 = make_float4(x2.x * c.x + x1.x * s.x, x2.y * c.y + x1.y * s.y,
                            x2.z * c.z + x1.z * s.z, x2.w * c.w + x1.w * s.w);
    *(float4*)(p)      = f2tf4(o1);
    *(float4*)(p + 64) = f2tf4(o2);
}

// ---------------- zero output ----------------
__global__ void zero_k(float* __restrict__ out) {
    ((float4*)out)[blockIdx.x * 256 + threadIdx.x] = make_float4(0.f, 0.f, 0.f, 0.f);
}

// ---------------- flash attention: cp.async staging of pre-processed Q/K/V ----------
#define QST 132
#define KST 132
#define PST 68
__global__ void __launch_bounds__(256, 2) attn_k(const float* __restrict__ alpha_p,
                                                 float* __restrict__ Out)
{
    extern __shared__ __align__(16) float sm[];
    float* Qs  = sm;                        // 64 x 132
    float* KVs = Qs + 64 * QST;             // 64 x 132
    float* Ps  = KVs + 64 * KST;            // 64 x 68
    float* wmx = Ps + 64 * PST;             // [2][64]
    float* wsp = wmx + 128;
    float* wsx = wsp + 128;

    int tid  = threadIdx.x;
    int lane = tid & 31, wid = tid >> 5;
    int gid  = lane >> 2, tig = lane & 3;
    int rg   = wid >> 1, half = wid & 1;
    int Q0 = blockIdx.x * 64;
    int b  = blockIdx.y;
    const float* Qb = g_Q + ((size_t)b * T_ + Q0) * HD;
    const float* Kb = g_K + (size_t)b * TKP * HD;
    const float* Vb = g_V + (size_t)b * TKP * HD;

    uint32_t sQ  = (uint32_t)__cvta_generic_to_shared(Qs);
    uint32_t sKV = (uint32_t)__cvta_generic_to_shared(KVs);
    int sr = tid >> 3, sc = tid & 7;    // 32 rows x 8 float4-cols per 256-thr iter

    // stage Q (pre-roped/scaled/rounded)
#pragma unroll
    for (int it = 0; it < 2; it++) {
        int r = sr + it * 32;
        cpa16(sQ + (uint32_t)((r * QST + sc * 4) * 4), Qb + (size_t)r * HD + sc * 4);
        cpa16(sQ + (uint32_t)((r * QST + 32 + sc * 4) * 4), Qb + (size_t)r * HD + 32 + sc * 4);
        cpa16(sQ + (uint32_t)((r * QST + 64 + sc * 4) * 4), Qb + (size_t)r * HD + 64 + sc * 4);
        cpa16(sQ + (uint32_t)((r * QST + 96 + sc * 4) * 4), Qb + (size_t)r * HD + 96 + sc * 4);
    }
    asm volatile("cp.async.commit_group;");

    int r0 = rg * 16 + gid, r1 = r0 + 8;
    int kmax0 = (Q0 + r0) >> 2, kmax1 = (Q0 + r1) >> 2;
    int bt = Q0 >> 8;
    int n0 = half * 32;
    int cc = half * 64;

    float m0r = -1e30f, m1r = -1e30f;
    float sp0 = 0.f, sp1 = 0.f, sx0 = 0.f, sx1 = 0.f;
    float Om[8][4], Ox[8][4];
#pragma unroll
    for (int nf = 0; nf < 8; nf++)
#pragma unroll
        for (int j = 0; j < 4; j++) { Om[nf][j] = 0.f; Ox[nf][j] = 0.f; }

    for (int kt = 0; kt < 16; kt++) {
        __syncthreads();                                    // (A) KVs/Ps free
        // stage K tile (pre-roped/rounded)
#pragma unroll
        for (int it = 0; it < 2; it++) {
            int r = sr + it * 32;
            const float* src = Kb + (size_t)(kt * 64 + r) * HD;
            cpa16(sKV + (uint32_t)((r * KST + sc * 4) * 4),      src + sc * 4);
            cpa16(sKV + (uint32_t)((r * KST + 32 + sc * 4) * 4), src + 32 + sc * 4);
            cpa16(sKV + (uint32_t)((r * KST + 64 + sc * 4) * 4), src + 64 + sc * 4);
            cpa16(sKV + (uint32_t)((r * KST + 96 + sc * 4) * 4), src + 96 + sc * 4);
        }
        asm volatile("cp.async.commit_group;");
        asm volatile("cp.async.wait_group 0;");
        __syncthreads();                                    // (B)

        // S = Q K^T (warp: 16 rows x 32 keys)
        float c[4][4];
#pragma unroll
        for (int nf = 0; nf < 4; nf++)
#pragma unroll
            for (int j = 0; j < 4; j++) c[nf][j] = 0.f;
#pragma unroll
        for (int ks = 0; ks < 16; ks++) {
            int k0 = ks * 8;
            float a0 = Qs[r0 * QST + k0 + tig];
            float a1 = Qs[r1 * QST + k0 + tig];
            float a2 = Qs[r0 * QST + k0 + tig + 4];
            float a3 = Qs[r1 * QST + k0 + tig + 4];
#pragma unroll
            for (int nf = 0; nf < 4; nf++) {
                const float* kp = KVs + (n0 + nf * 8 + gid) * KST + k0 + tig;
                mma8(c[nf], a0, a1, a2, a3, kp[0], kp[4]);
            }
        }
        float t0 = -1e30f, t1 = -1e30f;
#pragma unroll
        for (int nf = 0; nf < 4; nf++) {
            t0 = fmaxf(t0, fmaxf(c[nf][0], c[nf][1]));
            t1 = fmaxf(t1, fmaxf(c[nf][2], c[nf][3]));
        }
        t0 = fmaxf(t0, __shfl_xor_sync(0xffffffffu, t0, 1));
        t0 = fmaxf(t0, __shfl_xor_sync(0xffffffffu, t0, 2));
        t1 = fmaxf(t1, __shfl_xor_sync(0xffffffffu, t1, 1));
        t1 = fmaxf(t1, __shfl_xor_sync(0xffffffffu, t1, 2));
        if (tig == 0) { wmx[half * 64 + r0] = t0; wmx[half * 64 + r1] = t1; }
        __syncthreads();                                    // (C) all K reads done

        // stage V tile (pre-rounded) — overlaps softmax math below
#pragma unroll
        for (int it = 0; it < 2; it++) {
            int r = sr + it * 32;
            const float* src = Vb + (size_t)(kt * 64 + r) * HD;
            cpa16(sKV + (uint32_t)((r * KST + sc * 4) * 4),      src + sc * 4);
            cpa16(sKV + (uint32_t)((r * KST + 32 + sc * 4) * 4), src + 32 + sc * 4);
            cpa16(sKV + (uint32_t)((r * KST + 64 + sc * 4) * 4), src + 64 + sc * 4);
            cpa16(sKV + (uint32_t)((r * KST + 96 + sc * 4) * 4), src + 96 + sc * 4);
        }
        asm volatile("cp.async.commit_group;");

        float mn0 = fmaxf(m0r, fmaxf(wmx[r0], wmx[64 + r0]));
        float mn1 = fmaxf(m1r, fmaxf(wmx[r1], wmx[64 + r1]));
        float sc0 = __expf(m0r - mn0);
        float sc1 = __expf(m1r - mn1);
        m0r = mn0; m1r = mn1;
        sp0 *= sc0; sx0 *= sc0; sp1 *= sc1; sx1 *= sc1;
#pragma unroll
        for (int nf = 0; nf < 8; nf++) {
            Om[nf][0] *= sc0; Om[nf][1] *= sc0; Om[nf][2] *= sc1; Om[nf][3] *= sc1;
            Ox[nf][0] *= sc0; Ox[nf][1] *= sc0; Ox[nf][2] *= sc1; Ox[nf][3] *= sc1;
        }
        float lp0 = 0.f, lx0 = 0.f, lp1 = 0.f, lx1 = 0.f;
#pragma unroll
        for (int nf = 0; nf < 4; nf++) {
            int kl = n0 + nf * 8 + 2 * tig;
            int kg = kt * 64 + kl;
            float p0 = f2tf(__expf(c[nf][0] - mn0));
            float p1 = f2tf(__expf(c[nf][1] - mn0));
            float p2 = f2tf(__expf(c[nf][2] - mn1));
            float p3 = f2tf(__expf(c[nf][3] - mn1));
            *(float2*)(Ps + r0 * PST + kl) = make_float2(p0, p1);
            *(float2*)(Ps + r1 * PST + kl) = make_float2(p2, p3);
            if (kg     <= kmax0) lp0 += p0; else lx0 += p0;
            if (kg + 1 <= kmax0) lp0 += p1; else lx0 += p1;
            if (kg     <= kmax1) lp1 += p2; else lx1 += p2;
            if (kg + 1 <= kmax1) lp1 += p3; else lx1 += p3;
        }
        lp0 += __shfl_xor_sync(0xffffffffu, lp0, 1); lp0 += __shfl_xor_sync(0xffffffffu, lp0, 2);
        lx0 += __shfl_xor_sync(0xffffffffu, lx0, 1); lx0 += __shfl_xor_sync(0xffffffffu, lx0, 2);
        lp1 += __shfl_xor_sync(0xffffffffu, lp1, 1); lp1 += __shfl_xor_sync(0xffffffffu, lp1, 2);
        lx1 += __shfl_xor_sync(0xffffffffu, lx1, 1); lx1 += __shfl_xor_sync(0xffffffffu, lx1, 2);
        if (tig == 0) {
            wsp[half * 64 + r0] = lp0; wsp[half * 64 + r1] = lp1;
            wsx[half * 64 + r0] = lx0; wsx[half * 64 + r1] = lx1;
        }
        asm volatile("cp.async.wait_group 0;");
        __syncthreads();                                    // (D) P, V, sums ready

        sp0 += wsp[r0] + wsp[64 + r0];
        sp1 += wsp[r1] + wsp[64 + r1];
        sx0 += wsx[r0] + wsx[64 + r0];
        sx1 += wsx[r1] + wsx[64 + r1];

        if (kt < bt) {
#pragma unroll
            for (int ks = 0; ks < 8; ks++) {
                int k0 = ks * 8;
                float a0 = Ps[r0 * PST + k0 + tig];
                float a1 = Ps[r1 * PST + k0 + tig];
                float a2 = Ps[r0 * PST + k0 + tig + 4];
                float a3 = Ps[r1 * PST + k0 + tig + 4];
#pragma unroll
                for (int nf = 0; nf < 8; nf++) {
                    const float* vp = KVs + (k0 + tig) * KST + cc + nf * 8 + gid;
                    mma8(Om[nf], a0, a1, a2, a3, vp[0], vp[4 * KST]);
                }
            }
        } else if (kt > bt) {
#pragma unroll
            for (int ks = 0; ks < 8; ks++) {
                int k0 = ks * 8;
                float a0 = Ps[r0 * PST + k0 + tig];
                float a1 = Ps[r1 * PST + k0 + tig];
                float a2 = Ps[r0 * PST + k0 + tig + 4];
                float a3 = Ps[r1 * PST + k0 + tig + 4];
#pragma unroll
                for (int nf = 0; nf < 8; nf++) {
                    const float* vp = KVs + (k0 + tig) * KST + cc + nf * 8 + gid;
                    mma8(Ox[nf], a0, a1, a2, a3, vp[0], vp[4 * KST]);
                }
            }
        } else {
#pragma unroll
            for (int ks = 0; ks < 8; ks++) {
                int k0 = ks * 8;
                int kgA = kt * 64 + k0 + tig;
                int kgB = kgA + 4;
                float a0 = Ps[r0 * PST + k0 + tig];
                float a1 = Ps[r1 * PST + k0 + tig];
                float a2 = Ps[r0 * PST + k0 + tig + 4];
                float a3 = Ps[r1 * PST + k0 + tig + 4];
                float m0_ = (kgA <= kmax0) ? a0 : 0.f;
                float m1_ = (kgA <= kmax1) ? a1 : 0.f;
                float m2_ = (kgB <= kmax0) ? a2 : 0.f;
                float m3_ = (kgB <= kmax1) ? a3 : 0.f;
                float x0_ = a0 - m0_, x1_ = a1 - m1_, x2_ = a2 - m2_, x3_ = a3 - m3_;
#pragma unroll
                for (int nf = 0; nf < 8; nf++) {
                    const float* vp = KVs + (k0 + tig) * KST + cc + nf * 8 + gid;
                    float b0 = vp[0], b1 = vp[4 * KST];
                    mma8(Om[nf], m0_, m1_, m2_, m3_, b0, b1);
                    mma8(Ox[nf], x0_, x1_, x2_, x3_, b0, b1);
                }
            }
        }
    }

    // epilogue: atomic adds into zeroed Out (2 commutative adds/element -> deterministic)
    float alpha = 1.f / (1.f + __expf(-__ldg(alpha_p)));
    float wp0 = alpha / sp0;
    float wp1 = alpha / sp1;
    float wu0 = (1.f - alpha) / (sp0 + sx0);
    float wu1 = (1.f - alpha) / (sp1 + sx1);

    int qg0 = Q0 + r0, qg1 = Q0 + r1;
    float* O0 = Out + ((size_t)b * T_ + qg0) * HD;
    float* O1 = Out + ((size_t)b * T_ + qg1) * HD;
    float* U0 = Out + ((size_t)b * T_ + (T_ - 1 - qg0)) * HD;
    float* U1 = Out + ((size_t)b * T_ + (T_ - 1 - qg1)) * HD;
#pragma unroll
    for (int nf = 0; nf < 8; nf++) {
        int col = cc + nf * 8 + 2 * tig;
        atomicAdd(O0 + col,     Om[nf][0] * wp0);
        atomicAdd(O0 + col + 1, Om[nf][1] * wp0);
        atomicAdd(O1 + col,     Om[nf][2] * wp1);
        atomicAdd(O1 + col + 1, Om[nf][3] * wp1);
        atomicAdd(U0 + col,     (Om[nf][0] + Ox[nf][0]) * wu0);
        atomicAdd(U0 + col + 1, (Om[nf][1] + Ox[nf][1]) * wu0);
        atomicAdd(U1 + col,     (Om[nf][2] + Ox[nf][2]) * wu1);
        atomicAdd(U1 + col + 1, (Om[nf][3] + Ox[nf][3]) * wu1);
    }
}

// ---------------- launch ----------------
extern "C" void kernel_launch(void* const* d_in, const int* in_sizes, int n_in,
                              void* d_out, int out_size) {
    const float* x  = (const float*)d_in[0];
    const float* Wq = (const float*)d_in[1];
    const float* Wk = (const float*)d_in[2];
    const float* Wv = (const float*)d_in[3];
    const float* fa = (const float*)d_in[9];
    float* out = (float*)d_out;

    const int PROJ_SMEM = (2 * ABUF + 2 * BBUF) * 4;                              // 71680 B
    const int ATTN_SMEM = (64 * QST + 64 * KST + 64 * PST + 3 * 128) * 4;         // 86528 B
    cudaFuncSetAttribute(proj_k, cudaFuncAttributeMaxDynamicSharedMemorySize, PROJ_SMEM);
    cudaFuncSetAttribute(attn_k, cudaFuncAttributeMaxDynamicSharedMemorySize, ATTN_SMEM);

    theta_k<<<1, 64>>>();
    rope_table_k<<<T_, 64>>>();
    cvtW_k<<<384, 256>>>(Wq, Wk, Wv);
    pool_x_k<<<(B_ * TKP * (DM / 4)) / 256, 256>>>(x);
    proj_k<<<192, 256, PROJ_SMEM>>>(x);
    ropeq_k<<<(B_ * T_ * 16) / 256, 256>>>();
    ropek_k<<<(B_ * TKP * 16) / 256, 256>>>();
    zero_k<<<(B_ * T_ * HD / 4) / 256, 256>>>(out);
    attn_k<<<dim3(T_ / 64, B_), 256, ATTN_SMEM>>>(fa, out);
}

// round 7
// speedup vs baseline: 5.0370x; 1.1200x over previous
#include <cuda_runtime.h>
#include <cstdint>

#define B_  4
#define T_  4096
#define TKP 1024
#define DM  1024
#define HD  128
#define SCALE_INV 0.08838834764831845f   // 1/sqrt(128)

// ---------------- static device scratch ----------------
__device__ float  g_xp[B_ * TKP * DM];
__device__ float  g_Q [B_ * T_  * HD];   // d-dim interleaved [0,4,1,5,2,6,3,7] per 8-block
__device__ float  g_K [B_ * TKP * HD];   // d-dim interleaved
__device__ float  g_V [B_ * TKP * HD];   // normal layout
__device__ float  g_Wt[3 * DM * HD];     // tf32 weights, layout [which][kblk][n][8 interleaved]
__device__ float  g_cos[T_ * 64];
__device__ float  g_sin[T_ * 64];
__device__ double g_theta[64];

// ---------------- helpers ----------------
__device__ __forceinline__ unsigned f2t(float x) {
    unsigned r; asm("cvt.rna.tf32.f32 %0, %1;" : "=r"(r) : "f"(x)); return r;
}
__device__ __forceinline__ float f2tf(float x) { return __uint_as_float(f2t(x)); }
__device__ __forceinline__ float4 f2tf4(float4 v) {
    return make_float4(f2tf(v.x), f2tf(v.y), f2tf(v.z), f2tf(v.w));
}
__device__ __forceinline__ void mma8(float* d,
                                     float a0, float a1, float a2, float a3,
                                     float b0, float b1) {
    asm volatile("mma.sync.aligned.m16n8k8.row.col.f32.tf32.tf32.f32 "
                 "{%0,%1,%2,%3},{%4,%5,%6,%7},{%8,%9},{%0,%1,%2,%3};"
                 : "+f"(d[0]), "+f"(d[1]), "+f"(d[2]), "+f"(d[3])
                 : "r"(__float_as_uint(a0)), "r"(__float_as_uint(a1)),
                   "r"(__float_as_uint(a2)), "r"(__float_as_uint(a3)),
                   "r"(__float_as_uint(b0)), "r"(__float_as_uint(b1)));
}
__device__ __forceinline__ void cpa16(uint32_t dst, const void* src) {
    asm volatile("cp.async.cg.shared.global [%0], [%1], 16;" :: "r"(dst), "l"(src));
}

// ---------------- RoPE tables ----------------
__global__ void theta_k() {
    int i = threadIdx.x;
    g_theta[i] = exp(((double)(-i) / 64.0) * log(10000.0));
}
__global__ void rope_table_k() {
    int t = blockIdx.x, i = threadIdx.x;
    float thf = (float)g_theta[i];
    float arg = (float)t * thf;          // fp32 product, matching reference
    const double TWO_PI  = 6.283185307179586476925286766559;
    const double INV2PI  = 0.15915494309189533576888376337251;
    double da = (double)arg;
    double k  = rint(da * INV2PI);
    float  r  = (float)(da - k * TWO_PI);
    g_cos[t * 64 + i] = cosf(r);
    g_sin[t * 64 + i] = sinf(r);
}

// ---------------- weights -> tf32, layout [which][kblk][n][8 interleaved] ----------------
__global__ void cvtW_k(const float* __restrict__ Wq, const float* __restrict__ Wk,
                       const float* __restrict__ Wv) {
    int g = blockIdx.x * 256 + threadIdx.x;   // 3*128*128 = 49152 threads
    int n = g & 127;
    int kb = (g >> 7) & 127;
    int which = g >> 14;
    const float* W = (which == 0) ? Wq : (which == 1 ? Wk : Wv);
    float w[8];
#pragma unroll
    for (int j = 0; j < 8; j++) w[j] = f2tf(W[(size_t)(kb * 8 + j) * HD + n]);
    float* dst = g_Wt + (((size_t)which * 128 + kb) * 128 + n) * 8;
    *(float4*)(dst)     = make_float4(w[0], w[4], w[1], w[5]);
    *(float4*)(dst + 4) = make_float4(w[2], w[6], w[3], w[7]);
}

// ---------------- stride-4 mean pool (2 outputs/thread) ----------------
__global__ void pool_x_k(const float* __restrict__ x) {
    int f0 = (blockIdx.x * 256 + threadIdx.x) * 2;
    const float4* xi = (const float4*)x;
#pragma unroll
    for (int u = 0; u < 2; u++) {
        int f = f0 + u;
        int c4  = f & 255;
        int row = f >> 8;
        int b   = row >> 10, tp = row & 1023;
        size_t base = ((size_t)b * T_ + 4 * tp) * (DM / 4) + c4;
        float4 a = xi[base];
        float4 b2 = xi[base + (DM / 4)];
        float4 c = xi[base + 2 * (DM / 4)];
        float4 d = xi[base + 3 * (DM / 4)];
        float4 o;
        o.x = (a.x + b2.x + c.x + d.x) * 0.25f;
        o.y = (a.y + b2.y + c.y + d.y) * 0.25f;
        o.z = (a.z + b2.z + c.z + d.z) * 0.25f;
        o.w = (a.w + b2.w + c.w + d.w) * 0.25f;
        ((float4*)g_xp)[(size_t)row * (DM / 4) + c4] = o;
    }
}

// ---------------- projection GEMM: 1-term TF32, interleaved B, cp.async DB ----
#define AST 36
#define ABUF (128 * AST)
#define BBUF 4096                         // 4 kblk x 128 n x 8
__global__ void __launch_bounds__(256, 2) proj_k(const float* __restrict__ x) {
    extern __shared__ __align__(16) float psm[];
    float* As = psm;
    float* Bs = psm + 2 * ABUF;

    int bid = blockIdx.x;
    const float* A; const float* Wm; float* Cm; int m0; bool roundV = false;
    if (bid < 128)      { A = x;    Wm = g_Wt;                Cm = g_Q; m0 = bid * 128; }
    else if (bid < 160) { A = g_xp; Wm = g_Wt + DM * HD;      Cm = g_K; m0 = (bid - 128) * 128; }
    else                { A = g_xp; Wm = g_Wt + 2 * DM * HD;  Cm = g_V; m0 = (bid - 160) * 128; roundV = true; }

    int tid  = threadIdx.x;
    int lane = tid & 31, wid = tid >> 5;
    int gid  = lane >> 2, tig = lane & 3;
    int wm = wid >> 1, wn = wid & 1;

    uint32_t sA = (uint32_t)__cvta_generic_to_shared(As);
    uint32_t sB = (uint32_t)__cvta_generic_to_shared(Bs);
    int ar = tid >> 3, ac = tid & 7;

    auto stage = [&](int kb, int buf) {
#pragma unroll
        for (int it = 0; it < 4; it++) {
            int r = ar + it * 32;
            cpa16(sA + (uint32_t)((buf * ABUF + r * AST + ac * 4) * 4),
                  A + (size_t)(m0 + r) * DM + kb * 32 + ac * 4);
        }
        // B chunk: 4096 floats contiguous (kblk kb*4..+4, all n, interleaved 8)
#pragma unroll
        for (int it = 0; it < 4; it++) {
            int idx = it * 256 + tid;     // float4 index, 1024 total
            cpa16(sB + (uint32_t)((buf * BBUF + idx * 4) * 4),
                  Wm + (size_t)kb * 4096 + idx * 4);
        }
        asm volatile("cp.async.commit_group;");
    };

    float C[2][8][4];
#pragma unroll
    for (int mf = 0; mf < 2; mf++)
#pragma unroll
        for (int nf = 0; nf < 8; nf++)
#pragma unroll
            for (int j = 0; j < 4; j++) C[mf][nf][j] = 0.f;

    stage(0, 0);
    stage(1, 1);

    for (int kb = 0; kb < 32; kb++) {
        if (kb < 30) { asm volatile("cp.async.wait_group 1;"); }
        else         { asm volatile("cp.async.wait_group 0;"); }
        __syncthreads();
        const float* Ab = As + (kb & 1) * ABUF;
        const float* Bb = Bs + (kb & 1) * BBUF;
#pragma unroll
        for (int ks = 0; ks < 4; ks++) {
            int k0 = ks * 8;
            float ah[2][4];
#pragma unroll
            for (int mf = 0; mf < 2; mf++) {
                int mb = wm * 32 + mf * 16;
                ah[mf][0] = f2tf(Ab[(mb + gid)     * AST + k0 + tig]);
                ah[mf][1] = f2tf(Ab[(mb + gid + 8) * AST + k0 + tig]);
                ah[mf][2] = f2tf(Ab[(mb + gid)     * AST + k0 + tig + 4]);
                ah[mf][3] = f2tf(Ab[(mb + gid + 8) * AST + k0 + tig + 4]);
            }
#pragma unroll
            for (int nf = 0; nf < 8; nf++) {
                int nb = wn * 64 + nf * 8 + gid;
                float2 bb = *(const float2*)(Bb + (ks * 128 + nb) * 8 + 2 * tig);
#pragma unroll
                for (int mf = 0; mf < 2; mf++)
                    mma8(C[mf][nf], ah[mf][0], ah[mf][1], ah[mf][2], ah[mf][3], bb.x, bb.y);
            }
        }
        __syncthreads();
        if (kb + 2 < 32) stage(kb + 2, kb & 1);
    }

#pragma unroll
    for (int mf = 0; mf < 2; mf++) {
        int r0 = m0 + wm * 32 + mf * 16 + gid;
#pragma unroll
        for (int nf = 0; nf < 8; nf++) {
            int col = wn * 64 + nf * 8 + 2 * tig;
            float v0 = C[mf][nf][0], v1 = C[mf][nf][1];
            float v2 = C[mf][nf][2], v3 = C[mf][nf][3];
            if (roundV) { v0 = f2tf(v0); v1 = f2tf(v1); v2 = f2tf(v2); v3 = f2tf(v3); }
            *(float2*)(Cm + (size_t)r0 * HD + col)       = make_float2(v0, v1);
            *(float2*)(Cm + (size_t)(r0 + 8) * HD + col) = make_float2(v2, v3);
        }
    }
}

// ---------------- RoPE + tf32-round + d-interleave, in place ----------------
// Thread owns one 8-block b8 of the lower half (d = 8*b8..+8) and its +64 partner.
// Output positions within each 8-block: [o[0],o[4],o[1],o[5], o[2],o[6],o[3],o[7]].
__global__ void ropep_k(int which) {
    float* X   = which ? g_K : g_Q;
    int mask   = which ? (TKP - 1) : (T_ - 1);
    float scl  = which ? 1.f : SCALE_INV;
    int g  = blockIdx.x * 256 + threadIdx.x;
    int b8 = g & 7;
    int row = g >> 3;
    int pos = row & mask;
    const float4* cp = (const float4*)(g_cos + pos * 64 + b8 * 8);
    const float4* sp = (const float4*)(g_sin + pos * 64 + b8 * 8);
    float c[8], s[8], x1[8], x2[8];
    *(float4*)(c)     = cp[0]; *(float4*)(c + 4) = cp[1];
    *(float4*)(s)     = sp[0]; *(float4*)(s + 4) = sp[1];
    float* p = X + (size_t)row * HD + b8 * 8;
    *(float4*)(x1)     = *(float4*)(p);      *(float4*)(x1 + 4) = *(float4*)(p + 4);
    *(float4*)(x2)     = *(float4*)(p + 64); *(float4*)(x2 + 4) = *(float4*)(p + 68);
    float o1[8], o2[8];
#pragma unroll
    for (int j = 0; j < 8; j++) {
        o1[j] = (x1[j] * c[j] - x2[j] * s[j]) * scl;
        o2[j] = (x2[j] * c[j] + x1[j] * s[j]) * scl;
    }
    *(float4*)(p)      = f2tf4(make_float4(o1[0], o1[4], o1[1], o1[5]));
    *(float4*)(p + 4)  = f2tf4(make_float4(o1[2], o1[6], o1[3], o1[7]));
    *(float4*)(p + 64) = f2tf4(make_float4(o2[0], o2[4], o2[1], o2[5]));
    *(float4*)(p + 68) = f2tf4(make_float4(o2[2], o2[6], o2[3], o2[7]));
}

// ---------------- zero output ----------------
__global__ void zero_k(float* __restrict__ out) {
    ((float4*)out)[blockIdx.x * 256 + threadIdx.x] = make_float4(0.f, 0.f, 0.f, 0.f);
}

// ---------------- flash attention: interleaved Q/K frags (LDS.64), cp.async staging ----
#define QST 136
#define KST 136
#define PST 68
__global__ void __launch_bounds__(256, 2) attn_k(const float* __restrict__ alpha_p,
                                                 float* __restrict__ Out)
{
    extern __shared__ __align__(16) float sm[];
    float* Qs  = sm;                        // 64 x 136
    float* KVs = Qs + 64 * QST;             // 64 x 136
    float* Ps  = KVs + 64 * KST;            // 64 x 68
    float* wmx = Ps + 64 * PST;             // [2][64]
    float* wsp = wmx + 128;
    float* wsx = wsp + 128;

    int tid  = threadIdx.x;
    int lane = tid & 31, wid = tid >> 5;
    int gid  = lane >> 2, tig = lane & 3;
    int rg   = wid >> 1, half = wid & 1;
    int Q0 = blockIdx.x * 64;
    int b  = blockIdx.y;
    const float* Qb = g_Q + ((size_t)b * T_ + Q0) * HD;
    const float* Kb = g_K + (size_t)b * TKP * HD;
    const float* Vb = g_V + (size_t)b * TKP * HD;

    uint32_t sQ  = (uint32_t)__cvta_generic_to_shared(Qs);
    uint32_t sKV = (uint32_t)__cvta_generic_to_shared(KVs);
    int sr = tid >> 3, sc = tid & 7;

    // stage Q (pre-roped/scaled/rounded/interleaved)
#pragma unroll
    for (int it = 0; it < 2; it++) {
        int r = sr + it * 32;
        cpa16(sQ + (uint32_t)((r * QST + sc * 4) * 4),      Qb + (size_t)r * HD + sc * 4);
        cpa16(sQ + (uint32_t)((r * QST + 32 + sc * 4) * 4), Qb + (size_t)r * HD + 32 + sc * 4);
        cpa16(sQ + (uint32_t)((r * QST + 64 + sc * 4) * 4), Qb + (size_t)r * HD + 64 + sc * 4);
        cpa16(sQ + (uint32_t)((r * QST + 96 + sc * 4) * 4), Qb + (size_t)r * HD + 96 + sc * 4);
    }
    asm volatile("cp.async.commit_group;");

    int r0 = rg * 16 + gid, r1 = r0 + 8;
    int kmax0 = (Q0 + r0) >> 2, kmax1 = (Q0 + r1) >> 2;
    int bt = Q0 >> 8;
    int n0 = half * 32;
    int cc = half * 64;

    float m0r = -1e30f, m1r = -1e30f;
    float sp0 = 0.f, sp1 = 0.f, sx0 = 0.f, sx1 = 0.f;
    float Om[8][4], Ox[8][4];
#pragma unroll
    for (int nf = 0; nf < 8; nf++)
#pragma unroll
        for (int j = 0; j < 4; j++) { Om[nf][j] = 0.f; Ox[nf][j] = 0.f; }

    for (int kt = 0; kt < 16; kt++) {
        __syncthreads();                                    // (A)
        // stage K tile
#pragma unroll
        for (int it = 0; it < 2; it++) {
            int r = sr + it * 32;
            const float* src = Kb + (size_t)(kt * 64 + r) * HD;
            cpa16(sKV + (uint32_t)((r * KST + sc * 4) * 4),      src + sc * 4);
            cpa16(sKV + (uint32_t)((r * KST + 32 + sc * 4) * 4), src + 32 + sc * 4);
            cpa16(sKV + (uint32_t)((r * KST + 64 + sc * 4) * 4), src + 64 + sc * 4);
            cpa16(sKV + (uint32_t)((r * KST + 96 + sc * 4) * 4), src + 96 + sc * 4);
        }
        asm volatile("cp.async.commit_group;");
        asm volatile("cp.async.wait_group 0;");
        __syncthreads();                                    // (B)

        // S = Q K^T — interleaved frags: one LDS.64 per operand pair
        float c[4][4];
#pragma unroll
        for (int nf = 0; nf < 4; nf++)
#pragma unroll
            for (int j = 0; j < 4; j++) c[nf][j] = 0.f;
#pragma unroll
        for (int ks = 0; ks < 16; ks++) {
            int k0 = ks * 8;
            float2 qa0 = *(const float2*)(Qs + r0 * QST + k0 + 2 * tig);
            float2 qa1 = *(const float2*)(Qs + r1 * QST + k0 + 2 * tig);
#pragma unroll
            for (int nf = 0; nf < 4; nf++) {
                float2 kb2 = *(const float2*)(KVs + (n0 + nf * 8 + gid) * KST + k0 + 2 * tig);
                mma8(c[nf], qa0.x, qa1.x, qa0.y, qa1.y, kb2.x, kb2.y);
            }
        }
        float t0 = -1e30f, t1 = -1e30f;
#pragma unroll
        for (int nf = 0; nf < 4; nf++) {
            t0 = fmaxf(t0, fmaxf(c[nf][0], c[nf][1]));
            t1 = fmaxf(t1, fmaxf(c[nf][2], c[nf][3]));
        }
        t0 = fmaxf(t0, __shfl_xor_sync(0xffffffffu, t0, 1));
        t0 = fmaxf(t0, __shfl_xor_sync(0xffffffffu, t0, 2));
        t1 = fmaxf(t1, __shfl_xor_sync(0xffffffffu, t1, 1));
        t1 = fmaxf(t1, __shfl_xor_sync(0xffffffffu, t1, 2));
        if (tig == 0) { wmx[half * 64 + r0] = t0; wmx[half * 64 + r1] = t1; }
        __syncthreads();                                    // (C)

        // stage V tile (normal layout) — overlaps softmax math
#pragma unroll
        for (int it = 0; it < 2; it++) {
            int r = sr + it * 32;
            const float* src = Vb + (size_t)(kt * 64 + r) * HD;
            cpa16(sKV + (uint32_t)((r * KST + sc * 4) * 4),      src + sc * 4);
            cpa16(sKV + (uint32_t)((r * KST + 32 + sc * 4) * 4), src + 32 + sc * 4);
            cpa16(sKV + (uint32_t)((r * KST + 64 + sc * 4) * 4), src + 64 + sc * 4);
            cpa16(sKV + (uint32_t)((r * KST + 96 + sc * 4) * 4), src + 96 + sc * 4);
        }
        asm volatile("cp.async.commit_group;");

        float mn0 = fmaxf(m0r, fmaxf(wmx[r0], wmx[64 + r0]));
        float mn1 = fmaxf(m1r, fmaxf(wmx[r1], wmx[64 + r1]));
        float sc0 = __expf(m0r - mn0);
        float sc1 = __expf(m1r - mn1);
        m0r = mn0; m1r = mn1;
        sp0 *= sc0; sx0 *= sc0; sp1 *= sc1; sx1 *= sc1;
#pragma unroll
        for (int nf = 0; nf < 8; nf++) {
            Om[nf][0] *= sc0; Om[nf][1] *= sc0; Om[nf][2] *= sc1; Om[nf][3] *= sc1;
            Ox[nf][0] *= sc0; Ox[nf][1] *= sc0; Ox[nf][2] *= sc1; Ox[nf][3] *= sc1;
        }
        float lp0 = 0.f, lx0 = 0.f, lp1 = 0.f, lx1 = 0.f;
#pragma unroll
        for (int nf = 0; nf < 4; nf++) {
            int kl = n0 + nf * 8 + 2 * tig;
            int kg = kt * 64 + kl;
            float p0 = f2tf(__expf(c[nf][0] - mn0));
            float p1 = f2tf(__expf(c[nf][1] - mn0));
            float p2 = f2tf(__expf(c[nf][2] - mn1));
            float p3 = f2tf(__expf(c[nf][3] - mn1));
            *(float2*)(Ps + r0 * PST + kl) = make_float2(p0, p1);
            *(float2*)(Ps + r1 * PST + kl) = make_float2(p2, p3);
            if (kg     <= kmax0) lp0 += p0; else lx0 += p0;
            if (kg + 1 <= kmax0) lp0 += p1; else lx0 += p1;
            if (kg     <= kmax1) lp1 += p2; else lx1 += p2;
            if (kg + 1 <= kmax1) lp1 += p3; else lx1 += p3;
        }
        lp0 += __shfl_xor_sync(0xffffffffu, lp0, 1); lp0 += __shfl_xor_sync(0xffffffffu, lp0, 2);
        lx0 += __shfl_xor_sync(0xffffffffu, lx0, 1); lx0 += __shfl_xor_sync(0xffffffffu, lx0, 2);
        lp1 += __shfl_xor_sync(0xffffffffu, lp1, 1); lp1 += __shfl_xor_sync(0xffffffffu, lp1, 2);
        lx1 += __shfl_xor_sync(0xffffffffu, lx1, 1); lx1 += __shfl_xor_sync(0xffffffffu, lx1, 2);
        if (tig == 0) {
            wsp[half * 64 + r0] = lp0; wsp[half * 64 + r1] = lp1;
            wsx[half * 64 + r0] = lx0; wsx[half * 64 + r1] = lx1;
        }
        asm volatile("cp.async.wait_group 0;");
        __syncthreads();                                    // (D)

        sp0 += wsp[r0] + wsp[64 + r0];
        sp1 += wsp[r1] + wsp[64 + r1];
        sx0 += wsx[r0] + wsx[64 + r0];
        sx1 += wsx[r1] + wsx[64 + r1];

        if (kt < bt) {
#pragma unroll
            for (int ks = 0; ks < 8; ks++) {
                int k0 = ks * 8;
                float a0 = Ps[r0 * PST + k0 + tig];
                float a1 = Ps[r1 * PST + k0 + tig];
                float a2 = Ps[r0 * PST + k0 + tig + 4];
                float a3 = Ps[r1 * PST + k0 + tig + 4];
#pragma unroll
                for (int nf = 0; nf < 8; nf++) {
                    const float* vp = KVs + (k0 + tig) * KST + cc + nf * 8 + gid;
                    mma8(Om[nf], a0, a1, a2, a3, vp[0], vp[4 * KST]);
                }
            }
        } else if (kt > bt) {
#pragma unroll
            for (int ks = 0; ks < 8; ks++) {
                int k0 = ks * 8;
                float a0 = Ps[r0 * PST + k0 + tig];
                float a1 = Ps[r1 * PST + k0 + tig];
                float a2 = Ps[r0 * PST + k0 + tig + 4];
                float a3 = Ps[r1 * PST + k0 + tig + 4];
#pragma unroll
                for (int nf = 0; nf < 8; nf++) {
                    const float* vp = KVs + (k0 + tig) * KST + cc + nf * 8 + gid;
                    mma8(Ox[nf], a0, a1, a2, a3, vp[0], vp[4 * KST]);
                }
            }
        } else {
#pragma unroll
            for (int ks = 0; ks < 8; ks++) {
                int k0 = ks * 8;
                int kgA = kt * 64 + k0 + tig;
                int kgB = kgA + 4;
                float a0 = Ps[r0 * PST + k0 + tig];
                float a1 = Ps[r1 * PST + k0 + tig];
                float a2 = Ps[r0 * PST + k0 + tig + 4];
                float a3 = Ps[r1 * PST + k0 + tig + 4];
                float m0_ = (kgA <= kmax0) ? a0 : 0.f;
                float m1_ = (kgA <= kmax1) ? a1 : 0.f;
                float m2_ = (kgB <= kmax0) ? a2 : 0.f;
                float m3_ = (kgB <= kmax1) ? a3 : 0.f;
                float x0_ = a0 - m0_, x1_ = a1 - m1_, x2_ = a2 - m2_, x3_ = a3 - m3_;
#pragma unroll
                for (int nf = 0; nf < 8; nf++) {
                    const float* vp = KVs + (k0 + tig) * KST + cc + nf * 8 + gid;
                    float b0 = vp[0], b1 = vp[4 * KST];
                    mma8(Om[nf], m0_, m1_, m2_, m3_, b0, b1);
                    mma8(Ox[nf], x0_, x1_, x2_, x3_, b0, b1);
                }
            }
        }
    }

    // epilogue: atomic adds into zeroed Out
    float alpha = 1.f / (1.f + __expf(-__ldg(alpha_p)));
    float wp0 = alpha / sp0;
    float wp1 = alpha / sp1;
    float wu0 = (1.f - alpha) / (sp0 + sx0);
    float wu1 = (1.f - alpha) / (sp1 + sx1);

    int qg0 = Q0 + r0, qg1 = Q0 + r1;
    float* O0 = Out + ((size_t)b * T_ + qg0) * HD;
    float* O1 = Out + ((size_t)b * T_ + qg1) * HD;
    float* U0 = Out + ((size_t)b * T_ + (T_ - 1 - qg0)) * HD;
    float* U1 = Out + ((size_t)b * T_ + (T_ - 1 - qg1)) * HD;
#pragma unroll
    for (int nf = 0; nf < 8; nf++) {
        int col = cc + nf * 8 + 2 * tig;
        atomicAdd(O0 + col,     Om[nf][0] * wp0);
        atomicAdd(O0 + col + 1, Om[nf][1] * wp0);
        atomicAdd(O1 + col,     Om[nf][2] * wp1);
        atomicAdd(O1 + col + 1, Om[nf][3] * wp1);
        atomicAdd(U0 + col,     (Om[nf][0] + Ox[nf][0]) * wu0);
        atomicAdd(U0 + col + 1, (Om[nf][1] + Ox[nf][1]) * wu0);
        atomicAdd(U1 + col,     (Om[nf][2] + Ox[nf][2]) * wu1);
        atomicAdd(U1 + col + 1, (Om[nf][3] + Ox[nf][3]) * wu1);
    }
}

// ---------------- launch ----------------
extern "C" void kernel_launch(void* const* d_in, const int* in_sizes, int n_in,
                              void* d_out, int out_size) {
    const float* x  = (const float*)d_in[0];
    const float* Wq = (const float*)d_in[1];
    const float* Wk = (const float*)d_in[2];
    const float* Wv = (const float*)d_in[3];
    const float* fa = (const float*)d_in[9];
    float* out = (float*)d_out;

    const int PROJ_SMEM = (2 * ABUF + 2 * BBUF) * 4;                              // 69632 B
    const int ATTN_SMEM = (64 * QST + 64 * KST + 64 * PST + 3 * 128) * 4;         // 88576 B
    cudaFuncSetAttribute(proj_k, cudaFuncAttributeMaxDynamicSharedMemorySize, PROJ_SMEM);
    cudaFuncSetAttribute(attn_k, cudaFuncAttributeMaxDynamicSharedMemorySize, ATTN_SMEM);

    theta_k<<<1, 64>>>();
    rope_table_k<<<T_, 64>>>();
    cvtW_k<<<192, 256>>>(Wq, Wk, Wv);
    pool_x_k<<<(B_ * TKP * (DM / 4)) / 512, 256>>>(x);
    proj_k<<<192, 256, PROJ_SMEM>>>(x);
    ropep_k<<<(B_ * T_ * 8) / 256, 256>>>(0);
    ropep_k<<<(B_ * TKP * 8) / 256, 256>>>(1);
    zero_k<<<(B_ * T_ * HD / 4) / 256, 256>>>(out);
    attn_k<<<dim3(T_ / 64, B_), 256, ATTN_SMEM>>>(fa, out);
}